// round 1
// baseline (speedup 1.0000x reference)
#include <cuda_runtime.h>
#include <math.h>

// Problem constants
#define BB   2
#define NN   1024
#define CC   1152
#define HH   16
#define HD   72
#define C3   3456              // 3*C
#define NROWS (BB*HH*NN)       // 32768

// ---------------- scratch (static device globals; no allocation) ----------------
static __device__ float g_qkv [BB*NN*C3];   // (B,N,3C)  ~28.3 MB
static __device__ float g_attn[BB*NN*CC];   // (B,N,C)   ~9.4 MB
static __device__ float g_cosL[NROWS];
static __device__ float g_cosA[NROWS];

// ---------------- warp reductions (deterministic) ----------------
static __device__ __forceinline__ float warpSum(float v) {
    #pragma unroll
    for (int o = 16; o > 0; o >>= 1) v += __shfl_xor_sync(0xffffffffu, v, o);
    return v;
}
static __device__ __forceinline__ float warpMax(float v) {
    #pragma unroll
    for (int o = 16; o > 0; o >>= 1) v = fmaxf(v, __shfl_xor_sync(0xffffffffu, v, o));
    return v;
}

// ---------------- fp32 NT GEMM: C[m,n] = sum_k A[m,k]*B[n,k] + bias[n] ----------------
// BM=BN=128, BK=32, 256 threads, 8x8 microtile.
#define GBM 128
#define GBN 128
#define GBK 32
__global__ __launch_bounds__(256) void gemm_nt_bias(
    const float* __restrict__ A, const float* __restrict__ B,
    const float* __restrict__ bias, float* __restrict__ C,
    int M, int N, int K)
{
    __shared__ float As[GBK][GBM];
    __shared__ float Bs[GBK][GBN];

    const int tid = threadIdx.x;
    const int m0 = blockIdx.y * GBM;
    const int n0 = blockIdx.x * GBN;
    const int tm = tid >> 4;        // 0..15
    const int tn = tid & 15;        // 0..15

    float acc[8][8];
    #pragma unroll
    for (int i = 0; i < 8; i++)
        #pragma unroll
        for (int j = 0; j < 8; j++) acc[i][j] = 0.f;

    for (int k0 = 0; k0 < K; k0 += GBK) {
        // load 128x32 tiles of A and B (float4, K-contiguous => coalesced)
        #pragma unroll
        for (int it = 0; it < 4; it++) {
            int f   = tid + it * 256;      // float4 index 0..1023
            int row = f >> 3;              // 0..127
            int kq  = (f & 7) * 4;         // 0,4,...,28
            float4 va = *reinterpret_cast<const float4*>(&A[(size_t)(m0 + row) * K + k0 + kq]);
            As[kq + 0][row] = va.x; As[kq + 1][row] = va.y;
            As[kq + 2][row] = va.z; As[kq + 3][row] = va.w;
            float4 vb = *reinterpret_cast<const float4*>(&B[(size_t)(n0 + row) * K + k0 + kq]);
            Bs[kq + 0][row] = vb.x; Bs[kq + 1][row] = vb.y;
            Bs[kq + 2][row] = vb.z; Bs[kq + 3][row] = vb.w;
        }
        __syncthreads();

        #pragma unroll
        for (int k = 0; k < GBK; k++) {
            float af[8], bf[8];
            #pragma unroll
            for (int i = 0; i < 8; i++) af[i] = As[k][tm * 8 + i];
            #pragma unroll
            for (int j = 0; j < 8; j++) bf[j] = Bs[k][tn * 8 + j];
            #pragma unroll
            for (int i = 0; i < 8; i++)
                #pragma unroll
                for (int j = 0; j < 8; j++)
                    acc[i][j] = fmaf(af[i], bf[j], acc[i][j]);
        }
        __syncthreads();
    }

    #pragma unroll
    for (int i = 0; i < 8; i++) {
        size_t rowoff = (size_t)(m0 + tm * 8 + i) * N + n0;
        #pragma unroll
        for (int j = 0; j < 8; j++) {
            int n = tn * 8 + j;
            C[rowoff + n] = acc[i][j] + bias[n0 + n];
        }
    }
}

// ---------------- fused dual attention + alignment statistics ----------------
// grid = (N/32, B*H); block = 256 threads (8 warps x 4 rows).
// One pass over K/V tiles (TILE_M=32) with online softmax for both streams.
#define TM 32
#define SP 73   // padded row stride (gcd(73%32=9, 32)=1 -> conflict-free strided reads)

__global__ __launch_bounds__(256) void attn_dual_kernel(
    const float* __restrict__ kdino, const float* __restrict__ vdino)
{
    __shared__ float q_s [32 * SP];
    __shared__ float kd_s[TM * SP];
    __shared__ float ks_s[TM * SP];
    __shared__ float vd_s[TM * SP];
    __shared__ float vs_s[TM * SP];

    const int tid  = threadIdx.x;
    const int lane = tid & 31;
    const int warp = tid >> 5;
    const int bh   = blockIdx.y;        // 0..31
    const int b    = bh >> 4;
    const int h    = bh & 15;
    const int n0   = blockIdx.x * 32;
    const float scale = rsqrtf((float)HD);

    // stage Q rows for this block
    for (int idx = tid; idx < 32 * HD; idx += 256) {
        int r = idx / HD, d = idx - r * HD;
        q_s[r * SP + d] = g_qkv[(size_t)(b * NN + n0 + r) * C3 + h * HD + d];
    }

    const int wrow = warp * 4;   // this warp's 4 rows (block-local)

    float mxd[4], mxs[4], sumd[4], sums[4];
    float accd[4][3], accs[4][3];
    float Sdd[4], Sss[4], Ssd[4];
    #pragma unroll
    for (int r = 0; r < 4; r++) {
        mxd[r] = mxs[r] = -1e30f;
        sumd[r] = sums[r] = 0.f;
        Sdd[r] = Sss[r] = Ssd[r] = 0.f;
        #pragma unroll
        for (int i = 0; i < 3; i++) { accd[r][i] = 0.f; accs[r][i] = 0.f; }
    }

    for (int t = 0; t < NN / TM; t++) {
        __syncthreads();   // previous tile fully consumed
        const int mb = t * TM;
        for (int idx = tid; idx < TM * HD; idx += 256) {
            int m = idx / HD, d = idx - m * HD;
            size_t gd = (size_t)(bh * NN + mb + m) * HD + d;
            size_t gs = (size_t)(b * NN + mb + m) * C3 + h * HD + d;
            kd_s[m * SP + d] = kdino[gd];
            vd_s[m * SP + d] = vdino[gd];
            ks_s[m * SP + d] = g_qkv[gs + CC];
            vs_s[m * SP + d] = g_qkv[gs + 2 * CC];
        }
        __syncthreads();

        // ---- logits for tile: lane owns column m = mb + lane ----
        float ld[4] = {0.f, 0.f, 0.f, 0.f};
        float ls[4] = {0.f, 0.f, 0.f, 0.f};
        #pragma unroll 8
        for (int d = 0; d < HD; d++) {
            float kd = kd_s[lane * SP + d];
            float ks = ks_s[lane * SP + d];
            #pragma unroll
            for (int r = 0; r < 4; r++) {
                float qv = q_s[(wrow + r) * SP + d];
                ld[r] = fmaf(qv, kd, ld[r]);
                ls[r] = fmaf(qv, ks, ls[r]);
            }
        }

        float pd[4], ps[4];
        #pragma unroll
        for (int r = 0; r < 4; r++) {
            ld[r] *= scale; ls[r] *= scale;
            // cosine stats (softmax-free, scale-invariant)
            Sdd[r] = fmaf(ld[r], ld[r], Sdd[r]);
            Sss[r] = fmaf(ls[r], ls[r], Sss[r]);
            Ssd[r] = fmaf(ld[r], ls[r], Ssd[r]);
            // online softmax — dino
            {
                float nm = fmaxf(mxd[r], warpMax(ld[r]));
                float corr = __expf(mxd[r] - nm);
                mxd[r] = nm;
                pd[r] = __expf(ld[r] - nm);
                sumd[r] = fmaf(sumd[r], corr, warpSum(pd[r]));
                accd[r][0] *= corr; accd[r][1] *= corr; accd[r][2] *= corr;
            }
            // online softmax — sit
            {
                float nm = fmaxf(mxs[r], warpMax(ls[r]));
                float corr = __expf(mxs[r] - nm);
                mxs[r] = nm;
                ps[r] = __expf(ls[r] - nm);
                sums[r] = fmaf(sums[r], corr, warpSum(ps[r]));
                accs[r][0] *= corr; accs[r][1] *= corr; accs[r][2] *= corr;
            }
        }

        // ---- V accumulation: lane owns feature dims lane, lane+32, (lane+64 if lane<8) ----
        #pragma unroll 4
        for (int mm = 0; mm < TM; mm++) {
            float vd0 = vd_s[mm * SP + lane];
            float vd1 = vd_s[mm * SP + lane + 32];
            float vd2 = (lane < 8) ? vd_s[mm * SP + lane + 64] : 0.f;
            float vs0 = vs_s[mm * SP + lane];
            float vs1 = vs_s[mm * SP + lane + 32];
            float vs2 = (lane < 8) ? vs_s[mm * SP + lane + 64] : 0.f;
            #pragma unroll
            for (int r = 0; r < 4; r++) {
                float pdm = __shfl_sync(0xffffffffu, pd[r], mm);
                float psm = __shfl_sync(0xffffffffu, ps[r], mm);
                accd[r][0] = fmaf(pdm, vd0, accd[r][0]);
                accd[r][1] = fmaf(pdm, vd1, accd[r][1]);
                accd[r][2] = fmaf(pdm, vd2, accd[r][2]);
                accs[r][0] = fmaf(psm, vs0, accs[r][0]);
                accs[r][1] = fmaf(psm, vs1, accs[r][1]);
                accs[r][2] = fmaf(psm, vs2, accs[r][2]);
            }
        }
    }

    // ---- finalize rows ----
    const float EPS = 1e-12f;
    #pragma unroll
    for (int r = 0; r < 4; r++) {
        float sdd = warpSum(Sdd[r]);
        float sss = warpSum(Sss[r]);
        float ssd = warpSum(Ssd[r]);
        float cosL = ssd / (fmaxf(sqrtf(sdd), EPS) * fmaxf(sqrtf(sss), EPS));

        float ns2 = accs[r][0]*accs[r][0] + accs[r][1]*accs[r][1] + accs[r][2]*accs[r][2];
        float nd2 = accd[r][0]*accd[r][0] + accd[r][1]*accd[r][1] + accd[r][2]*accd[r][2];
        float dp  = accs[r][0]*accd[r][0] + accs[r][1]*accd[r][1] + accs[r][2]*accd[r][2];
        ns2 = warpSum(ns2); nd2 = warpSum(nd2); dp = warpSum(dp);
        float cosA = dp / (fmaxf(sqrtf(ns2), EPS) * fmaxf(sqrtf(nd2), EPS));

        int n = n0 + wrow + r;
        float inv = 1.0f / sums[r];
        float* orow = &g_attn[(size_t)(b * NN + n) * CC + h * HD];
        orow[lane]      = accs[r][0] * inv;
        orow[lane + 32] = accs[r][1] * inv;
        if (lane < 8) orow[lane + 64] = accs[r][2] * inv;
        if (lane == 0) {
            g_cosL[bh * NN + n] = cosL;
            g_cosA[bh * NN + n] = cosA;
        }
    }
}

// ---------------- deterministic loss reduction ----------------
__global__ __launch_bounds__(256) void loss_kernel(float* __restrict__ out, int out_size)
{
    __shared__ float sL[256], sA[256];
    int t = threadIdx.x;
    float aL = 0.f, aA = 0.f;
    for (int i = t; i < NROWS; i += 256) { aL += g_cosL[i]; aA += g_cosA[i]; }
    sL[t] = aL; sA[t] = aA;
    __syncthreads();
    for (int s = 128; s > 0; s >>= 1) {
        if (t < s) { sL[t] += sL[t + s]; sA[t] += sA[t + s]; }
        __syncthreads();
    }
    if (t == 0) {
        float meanL = sL[0] / (float)NROWS;
        float meanA = sA[0] / (float)NROWS;
        out[out_size - 1] = 1.5f - meanL - 0.5f * meanA;
    }
}

// ---------------- launch ----------------
extern "C" void kernel_launch(void* const* d_in, const int* in_sizes, int n_in,
                              void* d_out, int out_size)
{
    const float* x      = (const float*)d_in[0];
    const float* qkv_w  = (const float*)d_in[1];
    const float* qkv_b  = (const float*)d_in[2];
    const float* proj_w = (const float*)d_in[3];
    const float* proj_b = (const float*)d_in[4];
    const float* k_dino = (const float*)d_in[5];
    const float* v_dino = (const float*)d_in[6];
    float* out = (float*)d_out;

    float* qkvbuf  = nullptr;
    float* attnbuf = nullptr;
    cudaGetSymbolAddress((void**)&qkvbuf,  g_qkv);
    cudaGetSymbolAddress((void**)&attnbuf, g_attn);

    // 1) qkv = x @ qkv_w^T + qkv_b   (M=2048, N=3456, K=1152)
    {
        dim3 grid(C3 / GBN, (BB * NN) / GBM);
        gemm_nt_bias<<<grid, 256>>>(x, qkv_w, qkv_b, qkvbuf, BB * NN, C3, CC);
    }
    // 2) fused dual attention + alignment stats
    {
        dim3 grid(NN / 32, BB * HH);
        attn_dual_kernel<<<grid, 256>>>(k_dino, v_dino);
    }
    // 3) out = attn @ proj_w^T + proj_b   (M=2048, N=1152, K=1152)
    {
        dim3 grid(CC / GBN, (BB * NN) / GBM);
        gemm_nt_bias<<<grid, 256>>>(attnbuf, proj_w, proj_b, out, BB * NN, CC, CC);
    }
    // 4) distill loss -> last output element
    loss_kernel<<<1, 256>>>(out, out_size);
}

// round 3
// speedup vs baseline: 1.3595x; 1.3595x over previous
#include <cuda_runtime.h>
#include <cuda_bf16.h>
#include <math.h>
#include <cstdint>

// Problem constants
#define BB   2
#define NN   1024
#define CC   1152
#define HH   16
#define HD   72
#define C3   3456              // 3*C
#define NROWS (BB*HH*NN)       // 32768

// ---------------- scratch (static device globals; no allocation) ----------------
static __device__ float g_qkv [BB*NN*C3];   // (B,N,3C)  ~28.3 MB
static __device__ float g_attn[BB*NN*CC];   // (B,N,C)   ~9.4 MB
static __device__ float g_cosL[NROWS];
static __device__ float g_cosA[NROWS];

static __device__ __forceinline__ uint32_t smem_to_u32(const void* p) {
    uint32_t a;
    asm("{ .reg .u64 t; cvta.to.shared.u64 t, %1; cvt.u32.u64 %0, t; }" : "=r"(a) : "l"(p));
    return a;
}

// ---------------- mma.sync primitives (base-arch PTX, sm_80+) ----------------
static __device__ __forceinline__ void ldmatrix_x4(uint32_t addr, uint32_t& r0, uint32_t& r1, uint32_t& r2, uint32_t& r3) {
    asm volatile("ldmatrix.sync.aligned.m8n8.x4.shared.b16 {%0,%1,%2,%3}, [%4];"
                 : "=r"(r0), "=r"(r1), "=r"(r2), "=r"(r3) : "r"(addr));
}
static __device__ __forceinline__ void mma_bf16(float* d, const uint32_t* a, const uint32_t* b) {
    asm volatile("mma.sync.aligned.m16n8k16.row.col.f32.bf16.bf16.f32 "
                 "{%0,%1,%2,%3}, {%4,%5,%6,%7}, {%8,%9}, {%0,%1,%2,%3};"
                 : "+f"(d[0]), "+f"(d[1]), "+f"(d[2]), "+f"(d[3])
                 : "r"(a[0]), "r"(a[1]), "r"(a[2]), "r"(a[3]), "r"(b[0]), "r"(b[1]));
}

static __device__ __forceinline__ void cvt_hilo2(float a, float b, uint32_t& hi, uint32_t& lo)
{
    __nv_bfloat162 h = __floats2bfloat162_rn(a, b);
    float r0 = a - __low2float(h);
    float r1 = b - __high2float(h);
    __nv_bfloat162 l = __floats2bfloat162_rn(r0, r1);
    hi = *reinterpret_cast<uint32_t*>(&h);
    lo = *reinterpret_cast<uint32_t*>(&l);
}

// ---------------- bf16x3 NT GEMM via mma.sync: C[m,n]=sum_k A[m,k]B[n,k]+bias[n] ----------------
// CTA tile 128x128, BK=32 (fp32 in, hi/lo bf16 tiles in smem). 8 warps = 4(M) x 2(N),
// warp tile 32x64. Padded smem stride 40 bf16 (80B) -> conflict-free ldmatrix.
#define TBM 128
#define TBN 128
#define TKB 32
#define SKP 40            // smem row stride in bf16 elems (80 bytes)

__global__ __launch_bounds__(256) void gemm_mma_bias(
    const float* __restrict__ A, const float* __restrict__ B,
    const float* __restrict__ bias, float* __restrict__ C,
    int M, int N, int K)
{
    __shared__ __align__(16) __nv_bfloat16 sAh[TBM * SKP];
    __shared__ __align__(16) __nv_bfloat16 sAl[TBM * SKP];
    __shared__ __align__(16) __nv_bfloat16 sBh[TBN * SKP];
    __shared__ __align__(16) __nv_bfloat16 sBl[TBN * SKP];

    const int tid  = threadIdx.x;
    const int lane = tid & 31;
    const int wid  = tid >> 5;
    const int wm   = wid & 3;           // 0..3
    const int wn   = wid >> 2;          // 0..1
    const int m0 = blockIdx.y * TBM;
    const int n0 = blockIdx.x * TBN;

    const uint32_t uAh = smem_to_u32(sAh);
    const uint32_t uAl = smem_to_u32(sAl);
    const uint32_t uBh = smem_to_u32(sBh);
    const uint32_t uBl = smem_to_u32(sBl);

    // ldmatrix per-lane address components
    const int ar = lane & 15;                      // A row within 16
    const int ah = lane >> 4;                      // A k-half (0/1)
    const uint32_t aoff = (uint32_t)((wm * 32 + ar) * (SKP * 2) + ah * 16);
    const int br = (lane & 7) + ((lane >> 4) << 3);   // B row within 16
    const int bh = (lane >> 3) & 1;                   // B k-half
    const uint32_t boff = (uint32_t)((wn * 64 + br) * (SKP * 2) + bh * 16);

    // loader mapping: f = tid + it*256 ; row = f>>3 (0..127); kq = f&7 (float4 idx)
    const int lrow = tid >> 3;
    const int lkq  = tid & 7;

    float acc[2][8][4];
    #pragma unroll
    for (int i = 0; i < 2; i++)
        #pragma unroll
        for (int j = 0; j < 8; j++)
            #pragma unroll
            for (int q = 0; q < 4; q++) acc[i][j][q] = 0.f;

    const float* Abase = A + (size_t)m0 * K;
    const float* Bbase = B + (size_t)n0 * K;
    const int nt = K / TKB;

    float4 pa[4], pb[4];
    // prefetch tile 0
    #pragma unroll
    for (int it = 0; it < 4; it++) {
        int row = lrow + it * 32;
        pa[it] = *reinterpret_cast<const float4*>(Abase + (size_t)row * K + lkq * 4);
        pb[it] = *reinterpret_cast<const float4*>(Bbase + (size_t)row * K + lkq * 4);
    }

    for (int t = 0; t < nt; t++) {
        // convert staged regs -> smem hi/lo tiles
        #pragma unroll
        for (int it = 0; it < 4; it++) {
            int row = lrow + it * 32;
            uint32_t so = (uint32_t)(row * (SKP * 2) + lkq * 8);  // byte offset
            uint2 h, l;
            cvt_hilo2(pa[it].x, pa[it].y, h.x, l.x);
            cvt_hilo2(pa[it].z, pa[it].w, h.y, l.y);
            *reinterpret_cast<uint2*>((char*)sAh + so) = h;
            *reinterpret_cast<uint2*>((char*)sAl + so) = l;
            cvt_hilo2(pb[it].x, pb[it].y, h.x, l.x);
            cvt_hilo2(pb[it].z, pb[it].w, h.y, l.y);
            *reinterpret_cast<uint2*>((char*)sBh + so) = h;
            *reinterpret_cast<uint2*>((char*)sBl + so) = l;
        }
        __syncthreads();

        // prefetch next tile (latency hidden behind mma work)
        if (t + 1 < nt) {
            const float* An = Abase + (t + 1) * TKB;
            const float* Bn = Bbase + (t + 1) * TKB;
            #pragma unroll
            for (int it = 0; it < 4; it++) {
                int row = lrow + it * 32;
                pa[it] = *reinterpret_cast<const float4*>(An + (size_t)row * K + lkq * 4);
                pb[it] = *reinterpret_cast<const float4*>(Bn + (size_t)row * K + lkq * 4);
            }
        }

        #pragma unroll
        for (int ks = 0; ks < 2; ks++) {
            const uint32_t kso = ks * 32;   // 16 bf16 = 32 bytes
            uint32_t ahr[2][4], alr[2][4];
            #pragma unroll
            for (int i = 0; i < 2; i++) {
                uint32_t ad = aoff + (uint32_t)(i * 16 * SKP * 2) + kso;
                ldmatrix_x4(uAh + ad, ahr[i][0], ahr[i][1], ahr[i][2], ahr[i][3]);
                ldmatrix_x4(uAl + ad, alr[i][0], alr[i][1], alr[i][2], alr[i][3]);
            }
            uint32_t bhr[8][2], blr[8][2];
            #pragma unroll
            for (int g = 0; g < 4; g++) {
                uint32_t bd = boff + (uint32_t)(g * 16 * SKP * 2) + kso;
                uint32_t r0, r1, r2, r3;
                ldmatrix_x4(uBh + bd, r0, r1, r2, r3);
                bhr[2*g][0] = r0; bhr[2*g][1] = r1; bhr[2*g+1][0] = r2; bhr[2*g+1][1] = r3;
                ldmatrix_x4(uBl + bd, r0, r1, r2, r3);
                blr[2*g][0] = r0; blr[2*g][1] = r1; blr[2*g+1][0] = r2; blr[2*g+1][1] = r3;
            }
            #pragma unroll
            for (int i = 0; i < 2; i++)
                #pragma unroll
                for (int j = 0; j < 8; j++) {
                    mma_bf16(acc[i][j], ahr[i], bhr[j]);
                    mma_bf16(acc[i][j], ahr[i], blr[j]);
                    mma_bf16(acc[i][j], alr[i], bhr[j]);
                }
        }
        __syncthreads();
    }

    // epilogue: c0,c1 -> (row, col..col+1), c2,c3 -> (row+8, ...)
    const int cm = m0 + wm * 32 + (lane >> 2);
    const int cn = n0 + wn * 64 + (lane & 3) * 2;
    #pragma unroll
    for (int i = 0; i < 2; i++) {
        #pragma unroll
        for (int j = 0; j < 8; j++) {
            int nn = cn + j * 8;
            float2 b2 = *reinterpret_cast<const float2*>(bias + nn);
            float2 o0 = { acc[i][j][0] + b2.x, acc[i][j][1] + b2.y };
            float2 o1 = { acc[i][j][2] + b2.x, acc[i][j][3] + b2.y };
            *reinterpret_cast<float2*>(C + (size_t)(cm + i * 16    ) * N + nn) = o0;
            *reinterpret_cast<float2*>(C + (size_t)(cm + i * 16 + 8) * N + nn) = o1;
        }
    }
}

// ---------------- warp reductions (deterministic) ----------------
static __device__ __forceinline__ float warpSum(float v) {
    #pragma unroll
    for (int o = 16; o > 0; o >>= 1) v += __shfl_xor_sync(0xffffffffu, v, o);
    return v;
}
static __device__ __forceinline__ float warpMax(float v) {
    #pragma unroll
    for (int o = 16; o > 0; o >>= 1) v = fmaxf(v, __shfl_xor_sync(0xffffffffu, v, o));
    return v;
}

// ---------------- fused dual attention + alignment statistics ----------------
#define TM 32
#define SP 73

__global__ __launch_bounds__(256) void attn_dual_kernel(
    const float* __restrict__ kdino, const float* __restrict__ vdino)
{
    __shared__ float q_s [32 * SP];
    __shared__ float kd_s[TM * SP];
    __shared__ float ks_s[TM * SP];
    __shared__ float vd_s[TM * SP];
    __shared__ float vs_s[TM * SP];

    const int tid  = threadIdx.x;
    const int lane = tid & 31;
    const int warp = tid >> 5;
    const int bh   = blockIdx.y;
    const int b    = bh >> 4;
    const int h    = bh & 15;
    const int n0   = blockIdx.x * 32;
    const float scale = rsqrtf((float)HD);

    for (int idx = tid; idx < 32 * HD; idx += 256) {
        int r = idx / HD, d = idx - r * HD;
        q_s[r * SP + d] = g_qkv[(size_t)(b * NN + n0 + r) * C3 + h * HD + d];
    }

    const int wrow = warp * 4;

    float mxd[4], mxs[4], sumd[4], sums[4];
    float accd[4][3], accs[4][3];
    float Sdd[4], Sss[4], Ssd[4];
    #pragma unroll
    for (int r = 0; r < 4; r++) {
        mxd[r] = mxs[r] = -1e30f;
        sumd[r] = sums[r] = 0.f;
        Sdd[r] = Sss[r] = Ssd[r] = 0.f;
        #pragma unroll
        for (int i = 0; i < 3; i++) { accd[r][i] = 0.f; accs[r][i] = 0.f; }
    }

    for (int t = 0; t < NN / TM; t++) {
        __syncthreads();
        const int mb = t * TM;
        for (int idx = tid; idx < TM * HD; idx += 256) {
            int m = idx / HD, d = idx - m * HD;
            size_t gd = (size_t)(bh * NN + mb + m) * HD + d;
            size_t gs = (size_t)(b * NN + mb + m) * C3 + h * HD + d;
            kd_s[m * SP + d] = kdino[gd];
            vd_s[m * SP + d] = vdino[gd];
            ks_s[m * SP + d] = g_qkv[gs + CC];
            vs_s[m * SP + d] = g_qkv[gs + 2 * CC];
        }
        __syncthreads();

        float ld[4] = {0.f, 0.f, 0.f, 0.f};
        float ls[4] = {0.f, 0.f, 0.f, 0.f};
        #pragma unroll 8
        for (int d = 0; d < HD; d++) {
            float kd = kd_s[lane * SP + d];
            float ks = ks_s[lane * SP + d];
            #pragma unroll
            for (int r = 0; r < 4; r++) {
                float qv = q_s[(wrow + r) * SP + d];
                ld[r] = fmaf(qv, kd, ld[r]);
                ls[r] = fmaf(qv, ks, ls[r]);
            }
        }

        float pd[4], ps[4];
        #pragma unroll
        for (int r = 0; r < 4; r++) {
            ld[r] *= scale; ls[r] *= scale;
            Sdd[r] = fmaf(ld[r], ld[r], Sdd[r]);
            Sss[r] = fmaf(ls[r], ls[r], Sss[r]);
            Ssd[r] = fmaf(ld[r], ls[r], Ssd[r]);
            {
                float nm = fmaxf(mxd[r], warpMax(ld[r]));
                float corr = __expf(mxd[r] - nm);
                mxd[r] = nm;
                pd[r] = __expf(ld[r] - nm);
                sumd[r] = fmaf(sumd[r], corr, warpSum(pd[r]));
                accd[r][0] *= corr; accd[r][1] *= corr; accd[r][2] *= corr;
            }
            {
                float nm = fmaxf(mxs[r], warpMax(ls[r]));
                float corr = __expf(mxs[r] - nm);
                mxs[r] = nm;
                ps[r] = __expf(ls[r] - nm);
                sums[r] = fmaf(sums[r], corr, warpSum(ps[r]));
                accs[r][0] *= corr; accs[r][1] *= corr; accs[r][2] *= corr;
            }
        }

        #pragma unroll 4
        for (int mm = 0; mm < TM; mm++) {
            float vd0 = vd_s[mm * SP + lane];
            float vd1 = vd_s[mm * SP + lane + 32];
            float vd2 = (lane < 8) ? vd_s[mm * SP + lane + 64] : 0.f;
            float vs0 = vs_s[mm * SP + lane];
            float vs1 = vs_s[mm * SP + lane + 32];
            float vs2 = (lane < 8) ? vs_s[mm * SP + lane + 64] : 0.f;
            #pragma unroll
            for (int r = 0; r < 4; r++) {
                float pdm = __shfl_sync(0xffffffffu, pd[r], mm);
                float psm = __shfl_sync(0xffffffffu, ps[r], mm);
                accd[r][0] = fmaf(pdm, vd0, accd[r][0]);
                accd[r][1] = fmaf(pdm, vd1, accd[r][1]);
                accd[r][2] = fmaf(pdm, vd2, accd[r][2]);
                accs[r][0] = fmaf(psm, vs0, accs[r][0]);
                accs[r][1] = fmaf(psm, vs1, accs[r][1]);
                accs[r][2] = fmaf(psm, vs2, accs[r][2]);
            }
        }
    }

    const float EPS = 1e-12f;
    #pragma unroll
    for (int r = 0; r < 4; r++) {
        float sdd = warpSum(Sdd[r]);
        float sss = warpSum(Sss[r]);
        float ssd = warpSum(Ssd[r]);
        float cosL = ssd / (fmaxf(sqrtf(sdd), EPS) * fmaxf(sqrtf(sss), EPS));

        float ns2 = accs[r][0]*accs[r][0] + accs[r][1]*accs[r][1] + accs[r][2]*accs[r][2];
        float nd2 = accd[r][0]*accd[r][0] + accd[r][1]*accd[r][1] + accd[r][2]*accd[r][2];
        float dp  = accs[r][0]*accd[r][0] + accs[r][1]*accd[r][1] + accs[r][2]*accd[r][2];
        ns2 = warpSum(ns2); nd2 = warpSum(nd2); dp = warpSum(dp);
        float cosA = dp / (fmaxf(sqrtf(ns2), EPS) * fmaxf(sqrtf(nd2), EPS));

        int n = n0 + wrow + r;
        float inv = 1.0f / sums[r];
        float* orow = &g_attn[(size_t)(b * NN + n) * CC + h * HD];
        orow[lane]      = accs[r][0] * inv;
        orow[lane + 32] = accs[r][1] * inv;
        if (lane < 8) orow[lane + 64] = accs[r][2] * inv;
        if (lane == 0) {
            g_cosL[bh * NN + n] = cosL;
            g_cosA[bh * NN + n] = cosA;
        }
    }
}

// ---------------- deterministic loss reduction ----------------
__global__ __launch_bounds__(256) void loss_kernel(float* __restrict__ out, int out_size)
{
    __shared__ float sL[256], sA[256];
    int t = threadIdx.x;
    float aL = 0.f, aA = 0.f;
    for (int i = t; i < NROWS; i += 256) { aL += g_cosL[i]; aA += g_cosA[i]; }
    sL[t] = aL; sA[t] = aA;
    __syncthreads();
    for (int s = 128; s > 0; s >>= 1) {
        if (t < s) { sL[t] += sL[t + s]; sA[t] += sA[t + s]; }
        __syncthreads();
    }
    if (t == 0) {
        float meanL = sL[0] / (float)NROWS;
        float meanA = sA[0] / (float)NROWS;
        out[out_size - 1] = 1.5f - meanL - 0.5f * meanA;
    }
}

// ---------------- launch ----------------
extern "C" void kernel_launch(void* const* d_in, const int* in_sizes, int n_in,
                              void* d_out, int out_size)
{
    const float* x      = (const float*)d_in[0];
    const float* qkv_w  = (const float*)d_in[1];
    const float* qkv_b  = (const float*)d_in[2];
    const float* proj_w = (const float*)d_in[3];
    const float* proj_b = (const float*)d_in[4];
    const float* k_dino = (const float*)d_in[5];
    const float* v_dino = (const float*)d_in[6];
    float* out = (float*)d_out;

    float* qkvbuf  = nullptr;
    float* attnbuf = nullptr;
    cudaGetSymbolAddress((void**)&qkvbuf,  g_qkv);
    cudaGetSymbolAddress((void**)&attnbuf, g_attn);

    // 1) qkv = x @ qkv_w^T + qkv_b   (M=2048, N=3456, K=1152) — mma.sync bf16x3
    {
        dim3 grid(C3 / TBN, (BB * NN) / TBM);
        gemm_mma_bias<<<grid, 256>>>(x, qkv_w, qkv_b, qkvbuf, BB * NN, C3, CC);
    }
    // 2) fused dual attention + alignment stats
    {
        dim3 grid(NN / 32, BB * HH);
        attn_dual_kernel<<<grid, 256>>>(k_dino, v_dino);
    }
    // 3) out = attn @ proj_w^T + proj_b   (M=2048, N=1152, K=1152)
    {
        dim3 grid(CC / TBN, (BB * NN) / TBM);
        gemm_mma_bias<<<grid, 256>>>(attnbuf, proj_w, proj_b, out, BB * NN, CC, CC);
    }
    // 4) distill loss -> last output element
    loss_kernel<<<1, 256>>>(out, out_size);
}

// round 4
// speedup vs baseline: 3.0058x; 2.2109x over previous
#include <cuda_runtime.h>
#include <cuda_bf16.h>
#include <math.h>
#include <cstdint>

// Problem constants
#define BB   2
#define NN   1024
#define CC   1152
#define HH   16
#define HD   72
#define C3   3456              // 3*C
#define NROWS (BB*HH*NN)       // 32768

// ---------------- scratch (static device globals; no allocation) ----------------
static __device__ float g_qkv [BB*NN*C3];   // (B,N,3C)  ~28.3 MB
static __device__ float g_attn[BB*NN*CC];   // (B,N,C)   ~9.4 MB
static __device__ float g_cosL[NROWS];
static __device__ float g_cosA[NROWS];

static __device__ __forceinline__ uint32_t smem_to_u32(const void* p) {
    uint32_t a;
    asm("{ .reg .u64 t; cvta.to.shared.u64 t, %1; cvt.u32.u64 %0, t; }" : "=r"(a) : "l"(p));
    return a;
}

// ---------------- mma.sync primitives (base-arch PTX, sm_80+) ----------------
static __device__ __forceinline__ void ldmatrix_x4(uint32_t addr, uint32_t& r0, uint32_t& r1, uint32_t& r2, uint32_t& r3) {
    asm volatile("ldmatrix.sync.aligned.m8n8.x4.shared.b16 {%0,%1,%2,%3}, [%4];"
                 : "=r"(r0), "=r"(r1), "=r"(r2), "=r"(r3) : "r"(addr));
}
static __device__ __forceinline__ void ldmatrix_x4_trans(uint32_t addr, uint32_t& r0, uint32_t& r1, uint32_t& r2, uint32_t& r3) {
    asm volatile("ldmatrix.sync.aligned.m8n8.x4.trans.shared.b16 {%0,%1,%2,%3}, [%4];"
                 : "=r"(r0), "=r"(r1), "=r"(r2), "=r"(r3) : "r"(addr));
}
static __device__ __forceinline__ void mma_bf16(float* d, const uint32_t* a, const uint32_t* b) {
    asm volatile("mma.sync.aligned.m16n8k16.row.col.f32.bf16.bf16.f32 "
                 "{%0,%1,%2,%3}, {%4,%5,%6,%7}, {%8,%9}, {%0,%1,%2,%3};"
                 : "+f"(d[0]), "+f"(d[1]), "+f"(d[2]), "+f"(d[3])
                 : "r"(a[0]), "r"(a[1]), "r"(a[2]), "r"(a[3]), "r"(b[0]), "r"(b[1]));
}

static __device__ __forceinline__ void cvt_hilo2(float a, float b, uint32_t& hi, uint32_t& lo)
{
    __nv_bfloat162 h = __floats2bfloat162_rn(a, b);
    float r0 = a - __low2float(h);
    float r1 = b - __high2float(h);
    __nv_bfloat162 l = __floats2bfloat162_rn(r0, r1);
    hi = *reinterpret_cast<uint32_t*>(&h);
    lo = *reinterpret_cast<uint32_t*>(&l);
}

// ---------------- bf16x3 NT GEMM via mma.sync (unchanged from R3) ----------------
#define TBM 128
#define TBN 128
#define TKB 32
#define SKP 40            // smem row stride in bf16 elems (80 bytes)

__global__ __launch_bounds__(256) void gemm_mma_bias(
    const float* __restrict__ A, const float* __restrict__ B,
    const float* __restrict__ bias, float* __restrict__ C,
    int M, int N, int K)
{
    __shared__ __align__(16) __nv_bfloat16 sAh[TBM * SKP];
    __shared__ __align__(16) __nv_bfloat16 sAl[TBM * SKP];
    __shared__ __align__(16) __nv_bfloat16 sBh[TBN * SKP];
    __shared__ __align__(16) __nv_bfloat16 sBl[TBN * SKP];

    const int tid  = threadIdx.x;
    const int lane = tid & 31;
    const int wid  = tid >> 5;
    const int wm   = wid & 3;
    const int wn   = wid >> 2;
    const int m0 = blockIdx.y * TBM;
    const int n0 = blockIdx.x * TBN;

    const uint32_t uAh = smem_to_u32(sAh);
    const uint32_t uAl = smem_to_u32(sAl);
    const uint32_t uBh = smem_to_u32(sBh);
    const uint32_t uBl = smem_to_u32(sBl);

    const int ar = lane & 15;
    const int ah = lane >> 4;
    const uint32_t aoff = (uint32_t)((wm * 32 + ar) * (SKP * 2) + ah * 16);
    const int br = (lane & 7) + ((lane >> 4) << 3);
    const int bh = (lane >> 3) & 1;
    const uint32_t boff = (uint32_t)((wn * 64 + br) * (SKP * 2) + bh * 16);

    const int lrow = tid >> 3;
    const int lkq  = tid & 7;

    float acc[2][8][4];
    #pragma unroll
    for (int i = 0; i < 2; i++)
        #pragma unroll
        for (int j = 0; j < 8; j++)
            #pragma unroll
            for (int q = 0; q < 4; q++) acc[i][j][q] = 0.f;

    const float* Abase = A + (size_t)m0 * K;
    const float* Bbase = B + (size_t)n0 * K;
    const int nt = K / TKB;

    float4 pa[4], pb[4];
    #pragma unroll
    for (int it = 0; it < 4; it++) {
        int row = lrow + it * 32;
        pa[it] = *reinterpret_cast<const float4*>(Abase + (size_t)row * K + lkq * 4);
        pb[it] = *reinterpret_cast<const float4*>(Bbase + (size_t)row * K + lkq * 4);
    }

    for (int t = 0; t < nt; t++) {
        #pragma unroll
        for (int it = 0; it < 4; it++) {
            int row = lrow + it * 32;
            uint32_t so = (uint32_t)(row * (SKP * 2) + lkq * 8);
            uint2 h, l;
            cvt_hilo2(pa[it].x, pa[it].y, h.x, l.x);
            cvt_hilo2(pa[it].z, pa[it].w, h.y, l.y);
            *reinterpret_cast<uint2*>((char*)sAh + so) = h;
            *reinterpret_cast<uint2*>((char*)sAl + so) = l;
            cvt_hilo2(pb[it].x, pb[it].y, h.x, l.x);
            cvt_hilo2(pb[it].z, pb[it].w, h.y, l.y);
            *reinterpret_cast<uint2*>((char*)sBh + so) = h;
            *reinterpret_cast<uint2*>((char*)sBl + so) = l;
        }
        __syncthreads();

        if (t + 1 < nt) {
            const float* An = Abase + (t + 1) * TKB;
            const float* Bn = Bbase + (t + 1) * TKB;
            #pragma unroll
            for (int it = 0; it < 4; it++) {
                int row = lrow + it * 32;
                pa[it] = *reinterpret_cast<const float4*>(An + (size_t)row * K + lkq * 4);
                pb[it] = *reinterpret_cast<const float4*>(Bn + (size_t)row * K + lkq * 4);
            }
        }

        #pragma unroll
        for (int ks = 0; ks < 2; ks++) {
            const uint32_t kso = ks * 32;
            uint32_t ahr[2][4], alr[2][4];
            #pragma unroll
            for (int i = 0; i < 2; i++) {
                uint32_t ad = aoff + (uint32_t)(i * 16 * SKP * 2) + kso;
                ldmatrix_x4(uAh + ad, ahr[i][0], ahr[i][1], ahr[i][2], ahr[i][3]);
                ldmatrix_x4(uAl + ad, alr[i][0], alr[i][1], alr[i][2], alr[i][3]);
            }
            uint32_t bhr[8][2], blr[8][2];
            #pragma unroll
            for (int g = 0; g < 4; g++) {
                uint32_t bd = boff + (uint32_t)(g * 16 * SKP * 2) + kso;
                uint32_t r0, r1, r2, r3;
                ldmatrix_x4(uBh + bd, r0, r1, r2, r3);
                bhr[2*g][0] = r0; bhr[2*g][1] = r1; bhr[2*g+1][0] = r2; bhr[2*g+1][1] = r3;
                ldmatrix_x4(uBl + bd, r0, r1, r2, r3);
                blr[2*g][0] = r0; blr[2*g][1] = r1; blr[2*g+1][0] = r2; blr[2*g+1][1] = r3;
            }
            #pragma unroll
            for (int i = 0; i < 2; i++)
                #pragma unroll
                for (int j = 0; j < 8; j++) {
                    mma_bf16(acc[i][j], ahr[i], bhr[j]);
                    mma_bf16(acc[i][j], ahr[i], blr[j]);
                    mma_bf16(acc[i][j], alr[i], bhr[j]);
                }
        }
        __syncthreads();
    }

    const int cm = m0 + wm * 32 + (lane >> 2);
    const int cn = n0 + wn * 64 + (lane & 3) * 2;
    #pragma unroll
    for (int i = 0; i < 2; i++) {
        #pragma unroll
        for (int j = 0; j < 8; j++) {
            int nn = cn + j * 8;
            float2 b2 = *reinterpret_cast<const float2*>(bias + nn);
            float2 o0 = { acc[i][j][0] + b2.x, acc[i][j][1] + b2.y };
            float2 o1 = { acc[i][j][2] + b2.x, acc[i][j][3] + b2.y };
            *reinterpret_cast<float2*>(C + (size_t)(cm + i * 16    ) * N + nn) = o0;
            *reinterpret_cast<float2*>(C + (size_t)(cm + i * 16 + 8) * N + nn) = o1;
        }
    }
}

// =====================================================================
// Fused dual attention via mma.sync (flash-style, bf16x3)
// CTA: 128 q-rows of one (b,h). 8 warps x 16 rows. Key tile = 64.
// =====================================================================
#define QB  128
#define KT  64
#define SRB 176                 // smem row stride bytes (88 bf16) — conflict-free ldmatrix
#define AQ_HI 0
#define AQ_LO (QB*SRB)
#define AK_HI (2*QB*SRB)
#define AK_LO (AK_HI + KT*SRB)
#define AV_HI (AK_LO + KT*SRB)
#define AV_LO (AV_HI + KT*SRB)
#define ATTN_SMEM (AV_LO + KT*SRB)   // 90112 bytes

// S[8 n-tiles][4] = Q (16 rows) x K-tile (64 keys), hi/lo x3
static __device__ __forceinline__ void compute_logits(
    float s[8][4], uint32_t sb, uint32_t khi_off, uint32_t klo_off, int lane, int wq0)
{
    #pragma unroll
    for (int tt = 0; tt < 8; tt++)
        #pragma unroll
        for (int q = 0; q < 4; q++) s[tt][q] = 0.f;

    const uint32_t qaddr = sb + (uint32_t)((wq0 + (lane & 15)) * SRB + (lane >> 4) * 16);
    const int ksub = lane >> 3, ki = lane & 7;
    const uint32_t kn_row = (uint32_t)(((ksub >> 1) << 3) + ki);
    const uint32_t kk_half = (uint32_t)((ksub & 1) * 16);

    #pragma unroll
    for (int ks = 0; ks < 5; ks++) {
        uint32_t ahr[4], alr[4];
        ldmatrix_x4(qaddr + AQ_HI + ks * 32, ahr[0], ahr[1], ahr[2], ahr[3]);
        ldmatrix_x4(qaddr + AQ_LO + ks * 32, alr[0], alr[1], alr[2], alr[3]);
        #pragma unroll
        for (int g = 0; g < 4; g++) {
            uint32_t kaddr = sb + (uint32_t)((g * 16 + kn_row) * SRB + ks * 32) + kk_half;
            uint32_t bh_[4], bl_[4];
            ldmatrix_x4(kaddr + khi_off, bh_[0], bh_[1], bh_[2], bh_[3]);
            ldmatrix_x4(kaddr + klo_off, bl_[0], bl_[1], bl_[2], bl_[3]);
            mma_bf16(s[2*g],     ahr, bh_);
            mma_bf16(s[2*g],     ahr, bl_);
            mma_bf16(s[2*g],     alr, bh_);
            mma_bf16(s[2*g + 1], ahr, bh_ + 2);
            mma_bf16(s[2*g + 1], ahr, bl_ + 2);
            mma_bf16(s[2*g + 1], alr, bh_ + 2);
        }
    }
}

// Online softmax update + PV accumulate for one stream. s may alias p.
static __device__ __forceinline__ void softmax_pv(
    const float s[8][4], float p[8][4],
    float& m0, float& m1, float& l0, float& l1,
    float acc[9][4],
    uint32_t sb, uint32_t vhi_off, uint32_t vlo_off, int lane)
{
    float mx0 = -1e30f, mx1 = -1e30f;
    #pragma unroll
    for (int tt = 0; tt < 8; tt++) {
        mx0 = fmaxf(mx0, fmaxf(s[tt][0], s[tt][1]));
        mx1 = fmaxf(mx1, fmaxf(s[tt][2], s[tt][3]));
    }
    mx0 = fmaxf(mx0, __shfl_xor_sync(0xffffffffu, mx0, 1));
    mx0 = fmaxf(mx0, __shfl_xor_sync(0xffffffffu, mx0, 2));
    mx1 = fmaxf(mx1, __shfl_xor_sync(0xffffffffu, mx1, 1));
    mx1 = fmaxf(mx1, __shfl_xor_sync(0xffffffffu, mx1, 2));

    const float m0n = fmaxf(m0, mx0), m1n = fmaxf(m1, mx1);
    const float c0 = __expf(m0 - m0n), c1 = __expf(m1 - m1n);
    m0 = m0n; m1 = m1n;

    float r0 = 0.f, r1 = 0.f;
    #pragma unroll
    for (int tt = 0; tt < 8; tt++) {
        float p0 = __expf(s[tt][0] - m0n), p1 = __expf(s[tt][1] - m0n);
        float p2 = __expf(s[tt][2] - m1n), p3 = __expf(s[tt][3] - m1n);
        p[tt][0] = p0; p[tt][1] = p1; p[tt][2] = p2; p[tt][3] = p3;
        r0 += p0 + p1; r1 += p2 + p3;
    }
    r0 += __shfl_xor_sync(0xffffffffu, r0, 1);
    r0 += __shfl_xor_sync(0xffffffffu, r0, 2);
    r1 += __shfl_xor_sync(0xffffffffu, r1, 1);
    r1 += __shfl_xor_sync(0xffffffffu, r1, 2);
    l0 = l0 * c0 + r0;
    l1 = l1 * c1 + r1;

    #pragma unroll
    for (int tt = 0; tt < 9; tt++) {
        acc[tt][0] *= c0; acc[tt][1] *= c0;
        acc[tt][2] *= c1; acc[tt][3] *= c1;
    }

    // PV: P (16x64) x V (64x72)
    const int vsub = lane >> 3, vi = lane & 7;
    #pragma unroll
    for (int j = 0; j < 4; j++) {
        uint32_t ahi[4], alo[4];
        cvt_hilo2(p[2*j][0],     p[2*j][1],     ahi[0], alo[0]);
        cvt_hilo2(p[2*j][2],     p[2*j][3],     ahi[1], alo[1]);
        cvt_hilo2(p[2*j + 1][0], p[2*j + 1][1], ahi[2], alo[2]);
        cvt_hilo2(p[2*j + 1][2], p[2*j + 1][3], ahi[3], alo[3]);
        const uint32_t krow = (uint32_t)(16 * j + vi + (vsub & 1) * 8);
        #pragma unroll
        for (int dp = 0; dp < 5; dp++) {
            uint32_t vaddr = sb + krow * SRB + (uint32_t)(dp * 32 + (vsub >> 1) * 16);
            uint32_t vh[4], vl[4];
            ldmatrix_x4_trans(vaddr + vhi_off, vh[0], vh[1], vh[2], vh[3]);
            ldmatrix_x4_trans(vaddr + vlo_off, vl[0], vl[1], vl[2], vl[3]);
            mma_bf16(acc[2*dp], ahi, vh);
            mma_bf16(acc[2*dp], ahi, vl);
            mma_bf16(acc[2*dp], alo, vh);
            if (2*dp + 1 < 9) {
                mma_bf16(acc[2*dp + 1], ahi, vh + 2);
                mma_bf16(acc[2*dp + 1], ahi, vl + 2);
                mma_bf16(acc[2*dp + 1], alo, vh + 2);
            }
        }
    }
}

__global__ __launch_bounds__(256) void attn_mma_kernel(
    const float* __restrict__ kdino, const float* __restrict__ vdino)
{
    extern __shared__ char sm[];
    const uint32_t sb = smem_to_u32(sm);
    const int tid = threadIdx.x, lane = tid & 31, wid = tid >> 5;
    const int bh = blockIdx.y, b = bh >> 4, h = bh & 15;
    const int q0 = blockIdx.x * QB;
    const int wq0 = wid * 16;
    const float scale = 0.11785113019775793f;   // 1/sqrt(72)

    // zero pads: cols 72..79 (bytes 144..159) of every row of every buffer
    for (int r = tid; r < 2 * QB + 4 * KT; r += 256)
        *reinterpret_cast<uint4*>(sm + (size_t)r * SRB + 144) = make_uint4(0, 0, 0, 0);

    // stage Q (prescaled) as hi/lo bf16
    for (int i = tid; i < QB * 18; i += 256) {
        int row = i / 18, c4 = i % 18;
        float4 v = *reinterpret_cast<const float4*>(
            &g_qkv[(size_t)(b * NN + q0 + row) * C3 + h * HD + c4 * 4]);
        uint2 hh, ll;
        cvt_hilo2(v.x * scale, v.y * scale, hh.x, ll.x);
        cvt_hilo2(v.z * scale, v.w * scale, hh.y, ll.y);
        *reinterpret_cast<uint2*>(sm + AQ_HI + row * SRB + c4 * 8) = hh;
        *reinterpret_cast<uint2*>(sm + AQ_LO + row * SRB + c4 * 8) = ll;
    }

    float accd[9][4], accs[9][4];
    #pragma unroll
    for (int tt = 0; tt < 9; tt++)
        #pragma unroll
        for (int q = 0; q < 4; q++) { accd[tt][q] = 0.f; accs[tt][q] = 0.f; }
    float md0 = -1e30f, md1 = -1e30f, ms0 = -1e30f, ms1 = -1e30f;
    float ld0 = 0.f, ld1 = 0.f, ls0 = 0.f, ls1 = 0.f;
    float Sdd0 = 0.f, Sdd1 = 0.f, Sss0 = 0.f, Sss1 = 0.f, Ssd0 = 0.f, Ssd1 = 0.f;

    float sd[8][4], p[8][4];

    for (int t = 0; t < NN / KT; t++) {
        const int k0 = t * KT;

        // ---- phase D: load dino K/V, compute ----
        __syncthreads();
        for (int i = tid; i < KT * 18; i += 256) {
            int row = i / 18, c4 = i % 18;
            size_t g = (size_t)(bh * NN + k0 + row) * HD + c4 * 4;
            float4 kv = *reinterpret_cast<const float4*>(kdino + g);
            uint2 hh, ll;
            cvt_hilo2(kv.x, kv.y, hh.x, ll.x);
            cvt_hilo2(kv.z, kv.w, hh.y, ll.y);
            *reinterpret_cast<uint2*>(sm + AK_HI + row * SRB + c4 * 8) = hh;
            *reinterpret_cast<uint2*>(sm + AK_LO + row * SRB + c4 * 8) = ll;
            float4 vv = *reinterpret_cast<const float4*>(vdino + g);
            cvt_hilo2(vv.x, vv.y, hh.x, ll.x);
            cvt_hilo2(vv.z, vv.w, hh.y, ll.y);
            *reinterpret_cast<uint2*>(sm + AV_HI + row * SRB + c4 * 8) = hh;
            *reinterpret_cast<uint2*>(sm + AV_LO + row * SRB + c4 * 8) = ll;
        }
        __syncthreads();

        compute_logits(sd, sb, AK_HI, AK_LO, lane, wq0);
        softmax_pv(sd, p, md0, md1, ld0, ld1, accd, sb, AV_HI, AV_LO, lane);

        // ---- phase S: load sit K/V, compute ----
        __syncthreads();
        for (int i = tid; i < KT * 18; i += 256) {
            int row = i / 18, c4 = i % 18;
            size_t g = (size_t)(b * NN + k0 + row) * C3 + h * HD + c4 * 4;
            float4 kv = *reinterpret_cast<const float4*>(&g_qkv[g + CC]);
            uint2 hh, ll;
            cvt_hilo2(kv.x, kv.y, hh.x, ll.x);
            cvt_hilo2(kv.z, kv.w, hh.y, ll.y);
            *reinterpret_cast<uint2*>(sm + AK_HI + row * SRB + c4 * 8) = hh;
            *reinterpret_cast<uint2*>(sm + AK_LO + row * SRB + c4 * 8) = ll;
            float4 vv = *reinterpret_cast<const float4*>(&g_qkv[g + 2 * CC]);
            cvt_hilo2(vv.x, vv.y, hh.x, ll.x);
            cvt_hilo2(vv.z, vv.w, hh.y, ll.y);
            *reinterpret_cast<uint2*>(sm + AV_HI + row * SRB + c4 * 8) = hh;
            *reinterpret_cast<uint2*>(sm + AV_LO + row * SRB + c4 * 8) = ll;
        }
        __syncthreads();

        compute_logits(p, sb, AK_HI, AK_LO, lane, wq0);

        // cosine stats on raw (scaled) logits
        #pragma unroll
        for (int tt = 0; tt < 8; tt++) {
            Sdd0 = fmaf(sd[tt][0], sd[tt][0], Sdd0); Sdd0 = fmaf(sd[tt][1], sd[tt][1], Sdd0);
            Sdd1 = fmaf(sd[tt][2], sd[tt][2], Sdd1); Sdd1 = fmaf(sd[tt][3], sd[tt][3], Sdd1);
            Sss0 = fmaf(p[tt][0], p[tt][0], Sss0);   Sss0 = fmaf(p[tt][1], p[tt][1], Sss0);
            Sss1 = fmaf(p[tt][2], p[tt][2], Sss1);   Sss1 = fmaf(p[tt][3], p[tt][3], Sss1);
            Ssd0 = fmaf(sd[tt][0], p[tt][0], Ssd0);  Ssd0 = fmaf(sd[tt][1], p[tt][1], Ssd0);
            Ssd1 = fmaf(sd[tt][2], p[tt][2], Ssd1);  Ssd1 = fmaf(sd[tt][3], p[tt][3], Ssd1);
        }

        softmax_pv(p, p, ms0, ms1, ls0, ls1, accs, sb, AV_HI, AV_LO, lane);
    }

    // ---- finalize ----
    const float EPS = 1e-12f;
    const int r = lane >> 2, cq = (lane & 3) * 2;
    const int n0r = q0 + wq0 + r;
    const float inv0 = 1.0f / ls0, inv1 = 1.0f / ls1;
    float* o0 = &g_attn[(size_t)(b * NN + n0r) * CC + h * HD];
    float* o1 = &g_attn[(size_t)(b * NN + n0r + 8) * CC + h * HD];
    #pragma unroll
    for (int tt = 0; tt < 9; tt++) {
        int col = tt * 8 + cq;
        float2 w0 = { accs[tt][0] * inv0, accs[tt][1] * inv0 };
        float2 w1 = { accs[tt][2] * inv1, accs[tt][3] * inv1 };
        *reinterpret_cast<float2*>(o0 + col) = w0;
        *reinterpret_cast<float2*>(o1 + col) = w1;
    }

    // cosA from un-normalized accumulators (cosine is scale-invariant per row)
    float dd0 = 0.f, ss0 = 0.f, xs0 = 0.f, dd1 = 0.f, ss1 = 0.f, xs1 = 0.f;
    #pragma unroll
    for (int tt = 0; tt < 9; tt++) {
        dd0 = fmaf(accd[tt][0], accd[tt][0], dd0); dd0 = fmaf(accd[tt][1], accd[tt][1], dd0);
        ss0 = fmaf(accs[tt][0], accs[tt][0], ss0); ss0 = fmaf(accs[tt][1], accs[tt][1], ss0);
        xs0 = fmaf(accd[tt][0], accs[tt][0], xs0); xs0 = fmaf(accd[tt][1], accs[tt][1], xs0);
        dd1 = fmaf(accd[tt][2], accd[tt][2], dd1); dd1 = fmaf(accd[tt][3], accd[tt][3], dd1);
        ss1 = fmaf(accs[tt][2], accs[tt][2], ss1); ss1 = fmaf(accs[tt][3], accs[tt][3], ss1);
        xs1 = fmaf(accd[tt][2], accs[tt][2], xs1); xs1 = fmaf(accd[tt][3], accs[tt][3], xs1);
    }
    #pragma unroll
    for (int o = 1; o <= 2; o <<= 1) {
        Sdd0 += __shfl_xor_sync(0xffffffffu, Sdd0, o);
        Sss0 += __shfl_xor_sync(0xffffffffu, Sss0, o);
        Ssd0 += __shfl_xor_sync(0xffffffffu, Ssd0, o);
        Sdd1 += __shfl_xor_sync(0xffffffffu, Sdd1, o);
        Sss1 += __shfl_xor_sync(0xffffffffu, Sss1, o);
        Ssd1 += __shfl_xor_sync(0xffffffffu, Ssd1, o);
        dd0 += __shfl_xor_sync(0xffffffffu, dd0, o);
        ss0 += __shfl_xor_sync(0xffffffffu, ss0, o);
        xs0 += __shfl_xor_sync(0xffffffffu, xs0, o);
        dd1 += __shfl_xor_sync(0xffffffffu, dd1, o);
        ss1 += __shfl_xor_sync(0xffffffffu, ss1, o);
        xs1 += __shfl_xor_sync(0xffffffffu, xs1, o);
    }
    if ((lane & 3) == 0) {
        float cosL0 = Ssd0 / (fmaxf(sqrtf(Sdd0), EPS) * fmaxf(sqrtf(Sss0), EPS));
        float cosL1 = Ssd1 / (fmaxf(sqrtf(Sdd1), EPS) * fmaxf(sqrtf(Sss1), EPS));
        float cosA0 = xs0 / (fmaxf(sqrtf(dd0), EPS) * fmaxf(sqrtf(ss0), EPS));
        float cosA1 = xs1 / (fmaxf(sqrtf(dd1), EPS) * fmaxf(sqrtf(ss1), EPS));
        g_cosL[bh * NN + n0r]     = cosL0;
        g_cosL[bh * NN + n0r + 8] = cosL1;
        g_cosA[bh * NN + n0r]     = cosA0;
        g_cosA[bh * NN + n0r + 8] = cosA1;
    }
}

// ---------------- deterministic loss reduction ----------------
__global__ __launch_bounds__(256) void loss_kernel(float* __restrict__ out, int out_size)
{
    __shared__ float sL[256], sA[256];
    int t = threadIdx.x;
    float aL = 0.f, aA = 0.f;
    for (int i = t; i < NROWS; i += 256) { aL += g_cosL[i]; aA += g_cosA[i]; }
    sL[t] = aL; sA[t] = aA;
    __syncthreads();
    for (int s = 128; s > 0; s >>= 1) {
        if (t < s) { sL[t] += sL[t + s]; sA[t] += sA[t + s]; }
        __syncthreads();
    }
    if (t == 0) {
        float meanL = sL[0] / (float)NROWS;
        float meanA = sA[0] / (float)NROWS;
        out[out_size - 1] = 1.5f - meanL - 0.5f * meanA;
    }
}

// ---------------- launch ----------------
extern "C" void kernel_launch(void* const* d_in, const int* in_sizes, int n_in,
                              void* d_out, int out_size)
{
    const float* x      = (const float*)d_in[0];
    const float* qkv_w  = (const float*)d_in[1];
    const float* qkv_b  = (const float*)d_in[2];
    const float* proj_w = (const float*)d_in[3];
    const float* proj_b = (const float*)d_in[4];
    const float* k_dino = (const float*)d_in[5];
    const float* v_dino = (const float*)d_in[6];
    float* out = (float*)d_out;

    float* qkvbuf  = nullptr;
    float* attnbuf = nullptr;
    cudaGetSymbolAddress((void**)&qkvbuf,  g_qkv);
    cudaGetSymbolAddress((void**)&attnbuf, g_attn);

    cudaFuncSetAttribute(attn_mma_kernel, cudaFuncAttributeMaxDynamicSharedMemorySize, ATTN_SMEM);

    // 1) qkv = x @ qkv_w^T + qkv_b
    {
        dim3 grid(C3 / TBN, (BB * NN) / TBM);
        gemm_mma_bias<<<grid, 256>>>(x, qkv_w, qkv_b, qkvbuf, BB * NN, C3, CC);
    }
    // 2) fused dual attention + alignment stats (tensor cores)
    {
        dim3 grid(NN / QB, BB * HH);
        attn_mma_kernel<<<grid, 256, ATTN_SMEM>>>(k_dino, v_dino);
    }
    // 3) out = attn @ proj_w^T + proj_b
    {
        dim3 grid(CC / TBN, (BB * NN) / TBM);
        gemm_mma_bias<<<grid, 256>>>(attnbuf, proj_w, proj_b, out, BB * NN, CC, CC);
    }
    // 4) distill loss
    loss_kernel<<<1, 256>>>(out, out_size);
}

// round 5
// speedup vs baseline: 3.4413x; 1.1449x over previous
#include <cuda_runtime.h>
#include <cuda_bf16.h>
#include <math.h>
#include <cstdint>

// Problem constants
#define BB   2
#define NN   1024
#define CC   1152
#define HH   16
#define HD   72
#define C3   3456              // 3*C
#define NROWS (BB*HH*NN)       // 32768

// ---------------- scratch (static device globals; no allocation) ----------------
static __device__ float g_qkv [BB*NN*C3];   // (B,N,3C)
static __device__ float g_attn[BB*NN*CC];   // (B,N,C)
static __device__ float g_cosL[NROWS];
static __device__ float g_cosA[NROWS];

static __device__ __forceinline__ uint32_t smem_to_u32(const void* p) {
    uint32_t a;
    asm("{ .reg .u64 t; cvta.to.shared.u64 t, %1; cvt.u32.u64 %0, t; }" : "=r"(a) : "l"(p));
    return a;
}

// ---------------- mma.sync primitives (base-arch PTX, sm_80+) ----------------
static __device__ __forceinline__ void ldmatrix_x4(uint32_t addr, uint32_t& r0, uint32_t& r1, uint32_t& r2, uint32_t& r3) {
    asm volatile("ldmatrix.sync.aligned.m8n8.x4.shared.b16 {%0,%1,%2,%3}, [%4];"
                 : "=r"(r0), "=r"(r1), "=r"(r2), "=r"(r3) : "r"(addr));
}
static __device__ __forceinline__ void ldmatrix_x4_trans(uint32_t addr, uint32_t& r0, uint32_t& r1, uint32_t& r2, uint32_t& r3) {
    asm volatile("ldmatrix.sync.aligned.m8n8.x4.trans.shared.b16 {%0,%1,%2,%3}, [%4];"
                 : "=r"(r0), "=r"(r1), "=r"(r2), "=r"(r3) : "r"(addr));
}
static __device__ __forceinline__ void mma_bf16(float* d, const uint32_t* a, const uint32_t* b) {
    asm volatile("mma.sync.aligned.m16n8k16.row.col.f32.bf16.bf16.f32 "
                 "{%0,%1,%2,%3}, {%4,%5,%6,%7}, {%8,%9}, {%0,%1,%2,%3};"
                 : "+f"(d[0]), "+f"(d[1]), "+f"(d[2]), "+f"(d[3])
                 : "r"(a[0]), "r"(a[1]), "r"(a[2]), "r"(a[3]), "r"(b[0]), "r"(b[1]));
}

static __device__ __forceinline__ void cvt_hilo2(float a, float b, uint32_t& hi, uint32_t& lo)
{
    __nv_bfloat162 h = __floats2bfloat162_rn(a, b);
    float r0 = a - __low2float(h);
    float r1 = b - __high2float(h);
    __nv_bfloat162 l = __floats2bfloat162_rn(r0, r1);
    hi = *reinterpret_cast<uint32_t*>(&h);
    lo = *reinterpret_cast<uint32_t*>(&l);
}

// ---------------- bf16x3 NT GEMM: double-buffered, term-major mma ----------------
#define TBM 128
#define TBN 128
#define TKB 32
#define SKP 40                    // smem row stride in bf16 (80 bytes)
#define G_AH 0                    // byte offsets within a stage
#define G_AL 10240
#define G_BH 20480
#define G_BL 30720
#define G_STAGE 40960
#define GEMM_SMEM (2*G_STAGE)     // 81920 bytes dynamic

__global__ __launch_bounds__(256) void gemm_mma_bias(
    const float* __restrict__ A, const float* __restrict__ B,
    const float* __restrict__ bias, float* __restrict__ C,
    int M, int N, int K)
{
    extern __shared__ char gsm[];
    const uint32_t u0 = smem_to_u32(gsm);

    const int tid  = threadIdx.x;
    const int lane = tid & 31;
    const int wid  = tid >> 5;
    const int wm   = wid & 3;
    const int wn   = wid >> 2;
    const int m0 = blockIdx.y * TBM;
    const int n0 = blockIdx.x * TBN;

    const int ar = lane & 15;
    const int ah = lane >> 4;
    const uint32_t aoff = (uint32_t)((wm * 32 + ar) * (SKP * 2) + ah * 16);
    const int br = (lane & 7) + ((lane >> 4) << 3);
    const int bh = (lane >> 3) & 1;
    const uint32_t boff = (uint32_t)((wn * 64 + br) * (SKP * 2) + bh * 16);

    const int lrow = tid >> 3;
    const int lkq  = tid & 7;

    float acc[2][8][4];
    #pragma unroll
    for (int i = 0; i < 2; i++)
        #pragma unroll
        for (int j = 0; j < 8; j++)
            #pragma unroll
            for (int q = 0; q < 4; q++) acc[i][j][q] = 0.f;

    const float* Abase = A + (size_t)m0 * K;
    const float* Bbase = B + (size_t)n0 * K;
    const int nt = K / TKB;

    float4 ra[4], rb[4];
    #pragma unroll
    for (int it = 0; it < 4; it++) {
        int row = lrow + it * 32;
        ra[it] = *reinterpret_cast<const float4*>(Abase + (size_t)row * K + lkq * 4);
        rb[it] = *reinterpret_cast<const float4*>(Bbase + (size_t)row * K + lkq * 4);
    }
    // convert tile 0 into stage 0
    #pragma unroll
    for (int it = 0; it < 4; it++) {
        int row = lrow + it * 32;
        uint32_t so = (uint32_t)(row * (SKP * 2) + lkq * 8);
        uint2 h, l;
        cvt_hilo2(ra[it].x, ra[it].y, h.x, l.x);
        cvt_hilo2(ra[it].z, ra[it].w, h.y, l.y);
        *reinterpret_cast<uint2*>(gsm + G_AH + so) = h;
        *reinterpret_cast<uint2*>(gsm + G_AL + so) = l;
        cvt_hilo2(rb[it].x, rb[it].y, h.x, l.x);
        cvt_hilo2(rb[it].z, rb[it].w, h.y, l.y);
        *reinterpret_cast<uint2*>(gsm + G_BH + so) = h;
        *reinterpret_cast<uint2*>(gsm + G_BL + so) = l;
    }
    __syncthreads();

    for (int t = 0; t < nt; t++) {
        const uint32_t us = u0 + (uint32_t)((t & 1) * G_STAGE);
        const bool more = (t + 1 < nt);
        if (more) {
            const float* An = Abase + (t + 1) * TKB;
            const float* Bn = Bbase + (t + 1) * TKB;
            #pragma unroll
            for (int it = 0; it < 4; it++) {
                int row = lrow + it * 32;
                ra[it] = *reinterpret_cast<const float4*>(An + (size_t)row * K + lkq * 4);
                rb[it] = *reinterpret_cast<const float4*>(Bn + (size_t)row * K + lkq * 4);
            }
        }

        // mma phase on stage t&1, term-major (no back-to-back acc reuse)
        #pragma unroll
        for (int ks = 0; ks < 2; ks++) {
            const uint32_t kso = ks * 32;
            uint32_t ahr[2][4], alr[2][4];
            #pragma unroll
            for (int i = 0; i < 2; i++) {
                uint32_t ad = aoff + (uint32_t)(i * 16 * SKP * 2) + kso;
                ldmatrix_x4(us + G_AH + ad, ahr[i][0], ahr[i][1], ahr[i][2], ahr[i][3]);
                ldmatrix_x4(us + G_AL + ad, alr[i][0], alr[i][1], alr[i][2], alr[i][3]);
            }
            uint32_t bhr[8][2], blr[8][2];
            #pragma unroll
            for (int g = 0; g < 4; g++) {
                uint32_t bd = boff + (uint32_t)(g * 16 * SKP * 2) + kso;
                uint32_t r0, r1, r2, r3;
                ldmatrix_x4(us + G_BH + bd, r0, r1, r2, r3);
                bhr[2*g][0] = r0; bhr[2*g][1] = r1; bhr[2*g+1][0] = r2; bhr[2*g+1][1] = r3;
                ldmatrix_x4(us + G_BL + bd, r0, r1, r2, r3);
                blr[2*g][0] = r0; blr[2*g][1] = r1; blr[2*g+1][0] = r2; blr[2*g+1][1] = r3;
            }
            #pragma unroll
            for (int i = 0; i < 2; i++)
                #pragma unroll
                for (int j = 0; j < 8; j++) mma_bf16(acc[i][j], ahr[i], bhr[j]);
            #pragma unroll
            for (int i = 0; i < 2; i++)
                #pragma unroll
                for (int j = 0; j < 8; j++) mma_bf16(acc[i][j], ahr[i], blr[j]);
            #pragma unroll
            for (int i = 0; i < 2; i++)
                #pragma unroll
                for (int j = 0; j < 8; j++) mma_bf16(acc[i][j], alr[i], bhr[j]);
        }

        if (more) {
            char* nb = gsm + ((t + 1) & 1) * G_STAGE;
            #pragma unroll
            for (int it = 0; it < 4; it++) {
                int row = lrow + it * 32;
                uint32_t so = (uint32_t)(row * (SKP * 2) + lkq * 8);
                uint2 h, l;
                cvt_hilo2(ra[it].x, ra[it].y, h.x, l.x);
                cvt_hilo2(ra[it].z, ra[it].w, h.y, l.y);
                *reinterpret_cast<uint2*>(nb + G_AH + so) = h;
                *reinterpret_cast<uint2*>(nb + G_AL + so) = l;
                cvt_hilo2(rb[it].x, rb[it].y, h.x, l.x);
                cvt_hilo2(rb[it].z, rb[it].w, h.y, l.y);
                *reinterpret_cast<uint2*>(nb + G_BH + so) = h;
                *reinterpret_cast<uint2*>(nb + G_BL + so) = l;
            }
        }
        __syncthreads();
    }

    const int cm = m0 + wm * 32 + (lane >> 2);
    const int cn = n0 + wn * 64 + (lane & 3) * 2;
    #pragma unroll
    for (int i = 0; i < 2; i++) {
        #pragma unroll
        for (int j = 0; j < 8; j++) {
            int nn = cn + j * 8;
            float2 b2 = *reinterpret_cast<const float2*>(bias + nn);
            float2 o0 = { acc[i][j][0] + b2.x, acc[i][j][1] + b2.y };
            float2 o1 = { acc[i][j][2] + b2.x, acc[i][j][3] + b2.y };
            *reinterpret_cast<float2*>(C + (size_t)(cm + i * 16    ) * N + nn) = o0;
            *reinterpret_cast<float2*>(C + (size_t)(cm + i * 16 + 8) * N + nn) = o1;
        }
    }
}

// =====================================================================
// Fused dual attention via mma.sync (flash-style, bf16x3, term-major)
// CTA: 128 q-rows of one (b,h). 8 warps x 16 rows. Key tile = 64.
// Separate buffers per stream: one load phase + 2 barriers per tile.
// =====================================================================
#define QB  128
#define KT  64
#define SRB 176                 // smem row stride bytes (88 bf16)
#define AQ_HI 0
#define AQ_LO (QB*SRB)
#define DK_HI (2*QB*SRB)
#define DK_LO (DK_HI + KT*SRB)
#define DV_HI (DK_LO + KT*SRB)
#define DV_LO (DV_HI + KT*SRB)
#define SK_HI (DV_LO + KT*SRB)
#define SK_LO (SK_HI + KT*SRB)
#define SV_HI (SK_LO + KT*SRB)
#define SV_LO (SV_HI + KT*SRB)
#define ATTN_SMEM (SV_LO + KT*SRB)   // 135168 bytes

// S[8][4] = Q(16 rows) x K-tile(64 keys), hi/lo x3, term-major ordering
static __device__ __forceinline__ void compute_logits(
    float s[8][4], uint32_t sb, uint32_t khi_off, uint32_t klo_off, int lane, int wq0)
{
    #pragma unroll
    for (int tt = 0; tt < 8; tt++)
        #pragma unroll
        for (int q = 0; q < 4; q++) s[tt][q] = 0.f;

    const uint32_t qaddr = sb + (uint32_t)((wq0 + (lane & 15)) * SRB + (lane >> 4) * 16);
    const int ksub = lane >> 3, ki = lane & 7;
    const uint32_t kn_row = (uint32_t)(((ksub >> 1) << 3) + ki);
    const uint32_t kk_half = (uint32_t)((ksub & 1) * 16);

    #pragma unroll
    for (int ks = 0; ks < 5; ks++) {
        uint32_t ahr[4], alr[4];
        ldmatrix_x4(qaddr + AQ_HI + ks * 32, ahr[0], ahr[1], ahr[2], ahr[3]);
        ldmatrix_x4(qaddr + AQ_LO + ks * 32, alr[0], alr[1], alr[2], alr[3]);
        uint32_t bh_[8][2], bl_[8][2];
        #pragma unroll
        for (int g = 0; g < 4; g++) {
            uint32_t kaddr = sb + (uint32_t)((g * 16 + kn_row) * SRB + ks * 32) + kk_half;
            uint32_t r0, r1, r2, r3;
            ldmatrix_x4(kaddr + khi_off, r0, r1, r2, r3);
            bh_[2*g][0] = r0; bh_[2*g][1] = r1; bh_[2*g+1][0] = r2; bh_[2*g+1][1] = r3;
            ldmatrix_x4(kaddr + klo_off, r0, r1, r2, r3);
            bl_[2*g][0] = r0; bl_[2*g][1] = r1; bl_[2*g+1][0] = r2; bl_[2*g+1][1] = r3;
        }
        #pragma unroll
        for (int tt = 0; tt < 8; tt++) mma_bf16(s[tt], ahr, bh_[tt]);
        #pragma unroll
        for (int tt = 0; tt < 8; tt++) mma_bf16(s[tt], ahr, bl_[tt]);
        #pragma unroll
        for (int tt = 0; tt < 8; tt++) mma_bf16(s[tt], alr, bh_[tt]);
    }
}

// Online softmax update + PV accumulate. s may alias p.
static __device__ __forceinline__ void softmax_pv(
    const float s[8][4], float p[8][4],
    float& m0, float& m1, float& l0, float& l1,
    float acc[9][4],
    uint32_t sb, uint32_t vhi_off, uint32_t vlo_off, int lane)
{
    float mx0 = -1e30f, mx1 = -1e30f;
    #pragma unroll
    for (int tt = 0; tt < 8; tt++) {
        mx0 = fmaxf(mx0, fmaxf(s[tt][0], s[tt][1]));
        mx1 = fmaxf(mx1, fmaxf(s[tt][2], s[tt][3]));
    }
    mx0 = fmaxf(mx0, __shfl_xor_sync(0xffffffffu, mx0, 1));
    mx0 = fmaxf(mx0, __shfl_xor_sync(0xffffffffu, mx0, 2));
    mx1 = fmaxf(mx1, __shfl_xor_sync(0xffffffffu, mx1, 1));
    mx1 = fmaxf(mx1, __shfl_xor_sync(0xffffffffu, mx1, 2));

    const float m0n = fmaxf(m0, mx0), m1n = fmaxf(m1, mx1);
    const float c0 = __expf(m0 - m0n), c1 = __expf(m1 - m1n);
    m0 = m0n; m1 = m1n;

    float r0 = 0.f, r1 = 0.f;
    #pragma unroll
    for (int tt = 0; tt < 8; tt++) {
        float p0 = __expf(s[tt][0] - m0n), p1 = __expf(s[tt][1] - m0n);
        float p2 = __expf(s[tt][2] - m1n), p3 = __expf(s[tt][3] - m1n);
        p[tt][0] = p0; p[tt][1] = p1; p[tt][2] = p2; p[tt][3] = p3;
        r0 += p0 + p1; r1 += p2 + p3;
    }
    r0 += __shfl_xor_sync(0xffffffffu, r0, 1);
    r0 += __shfl_xor_sync(0xffffffffu, r0, 2);
    r1 += __shfl_xor_sync(0xffffffffu, r1, 1);
    r1 += __shfl_xor_sync(0xffffffffu, r1, 2);
    l0 = l0 * c0 + r0;
    l1 = l1 * c1 + r1;

    #pragma unroll
    for (int tt = 0; tt < 9; tt++) {
        acc[tt][0] *= c0; acc[tt][1] *= c0;
        acc[tt][2] *= c1; acc[tt][3] *= c1;
    }

    // PV: P (16x64) x V (64x72), dp-pair interleaving for acc-reuse distance 4
    const int vsub = lane >> 3, vi = lane & 7;
    #pragma unroll
    for (int j = 0; j < 4; j++) {
        uint32_t ahi[4], alo[4];
        cvt_hilo2(p[2*j][0],     p[2*j][1],     ahi[0], alo[0]);
        cvt_hilo2(p[2*j][2],     p[2*j][3],     ahi[1], alo[1]);
        cvt_hilo2(p[2*j + 1][0], p[2*j + 1][1], ahi[2], alo[2]);
        cvt_hilo2(p[2*j + 1][2], p[2*j + 1][3], ahi[3], alo[3]);
        const uint32_t krow = (uint32_t)(16 * j + vi + (vsub & 1) * 8);
        const uint32_t vrowa = sb + krow * SRB + (uint32_t)((vsub >> 1) * 16);
        #pragma unroll
        for (int dpp = 0; dpp < 2; dpp++) {
            uint32_t va0 = vrowa + (uint32_t)(2 * dpp * 32);
            uint32_t va1 = va0 + 32;
            uint32_t vh0[4], vl0[4], vh1[4], vl1[4];
            ldmatrix_x4_trans(va0 + vhi_off, vh0[0], vh0[1], vh0[2], vh0[3]);
            ldmatrix_x4_trans(va0 + vlo_off, vl0[0], vl0[1], vl0[2], vl0[3]);
            ldmatrix_x4_trans(va1 + vhi_off, vh1[0], vh1[1], vh1[2], vh1[3]);
            ldmatrix_x4_trans(va1 + vlo_off, vl1[0], vl1[1], vl1[2], vl1[3]);
            float* a0 = acc[4*dpp+0]; float* a1 = acc[4*dpp+1];
            float* a2 = acc[4*dpp+2]; float* a3 = acc[4*dpp+3];
            mma_bf16(a0, ahi, vh0); mma_bf16(a1, ahi, vh0 + 2);
            mma_bf16(a2, ahi, vh1); mma_bf16(a3, ahi, vh1 + 2);
            mma_bf16(a0, ahi, vl0); mma_bf16(a1, ahi, vl0 + 2);
            mma_bf16(a2, ahi, vl1); mma_bf16(a3, ahi, vl1 + 2);
            mma_bf16(a0, alo, vh0); mma_bf16(a1, alo, vh0 + 2);
            mma_bf16(a2, alo, vh1); mma_bf16(a3, alo, vh1 + 2);
        }
        // dp = 4 tail (dims 64..71): acc[8] only
        {
            uint32_t va = vrowa + 128;
            uint32_t vh[4], vl[4];
            ldmatrix_x4_trans(va + vhi_off, vh[0], vh[1], vh[2], vh[3]);
            ldmatrix_x4_trans(va + vlo_off, vl[0], vl[1], vl[2], vl[3]);
            mma_bf16(acc[8], ahi, vh);
            mma_bf16(acc[8], ahi, vl);
            mma_bf16(acc[8], alo, vh);
        }
    }
}

__global__ __launch_bounds__(256) void attn_mma_kernel(
    const float* __restrict__ kdino, const float* __restrict__ vdino)
{
    extern __shared__ char sm[];
    const uint32_t sb = smem_to_u32(sm);
    const int tid = threadIdx.x, lane = tid & 31, wid = tid >> 5;
    const int bh = blockIdx.y, b = bh >> 4, h = bh & 15;
    const int q0 = blockIdx.x * QB;
    const int wq0 = wid * 16;
    const float scale = 0.11785113019775793f;   // 1/sqrt(72)

    // zero pads: cols 72..79 (bytes 144..159) of every row of every buffer
    for (int r = tid; r < 2 * QB + 8 * KT; r += 256)
        *reinterpret_cast<uint4*>(sm + (size_t)r * SRB + 144) = make_uint4(0, 0, 0, 0);

    // stage Q (prescaled) as hi/lo bf16
    for (int i = tid; i < QB * 18; i += 256) {
        int row = i / 18, c4 = i % 18;
        float4 v = *reinterpret_cast<const float4*>(
            &g_qkv[(size_t)(b * NN + q0 + row) * C3 + h * HD + c4 * 4]);
        uint2 hh, ll;
        cvt_hilo2(v.x * scale, v.y * scale, hh.x, ll.x);
        cvt_hilo2(v.z * scale, v.w * scale, hh.y, ll.y);
        *reinterpret_cast<uint2*>(sm + AQ_HI + row * SRB + c4 * 8) = hh;
        *reinterpret_cast<uint2*>(sm + AQ_LO + row * SRB + c4 * 8) = ll;
    }

    float accd[9][4], accs[9][4];
    #pragma unroll
    for (int tt = 0; tt < 9; tt++)
        #pragma unroll
        for (int q = 0; q < 4; q++) { accd[tt][q] = 0.f; accs[tt][q] = 0.f; }
    float md0 = -1e30f, md1 = -1e30f, ms0 = -1e30f, ms1 = -1e30f;
    float ld0 = 0.f, ld1 = 0.f, ls0 = 0.f, ls1 = 0.f;
    float Sdd0 = 0.f, Sdd1 = 0.f, Sss0 = 0.f, Sss1 = 0.f, Ssd0 = 0.f, Ssd1 = 0.f;

    float sd[8][4], p[8][4];

    for (int t = 0; t < NN / KT; t++) {
        const int k0 = t * KT;

        __syncthreads();   // previous tile fully consumed
        // ---- single load phase: both streams' K/V ----
        for (int i = tid; i < KT * 18; i += 256) {
            int row = i / 18, c4 = i % 18;
            size_t gd = (size_t)(bh * NN + k0 + row) * HD + c4 * 4;
            float4 kv = *reinterpret_cast<const float4*>(kdino + gd);
            uint2 hh, ll;
            cvt_hilo2(kv.x, kv.y, hh.x, ll.x);
            cvt_hilo2(kv.z, kv.w, hh.y, ll.y);
            *reinterpret_cast<uint2*>(sm + DK_HI + row * SRB + c4 * 8) = hh;
            *reinterpret_cast<uint2*>(sm + DK_LO + row * SRB + c4 * 8) = ll;
            float4 vv = *reinterpret_cast<const float4*>(vdino + gd);
            cvt_hilo2(vv.x, vv.y, hh.x, ll.x);
            cvt_hilo2(vv.z, vv.w, hh.y, ll.y);
            *reinterpret_cast<uint2*>(sm + DV_HI + row * SRB + c4 * 8) = hh;
            *reinterpret_cast<uint2*>(sm + DV_LO + row * SRB + c4 * 8) = ll;

            size_t gs = (size_t)(b * NN + k0 + row) * C3 + h * HD + c4 * 4;
            float4 ks = *reinterpret_cast<const float4*>(&g_qkv[gs + CC]);
            cvt_hilo2(ks.x, ks.y, hh.x, ll.x);
            cvt_hilo2(ks.z, ks.w, hh.y, ll.y);
            *reinterpret_cast<uint2*>(sm + SK_HI + row * SRB + c4 * 8) = hh;
            *reinterpret_cast<uint2*>(sm + SK_LO + row * SRB + c4 * 8) = ll;
            float4 vs = *reinterpret_cast<const float4*>(&g_qkv[gs + 2 * CC]);
            cvt_hilo2(vs.x, vs.y, hh.x, ll.x);
            cvt_hilo2(vs.z, vs.w, hh.y, ll.y);
            *reinterpret_cast<uint2*>(sm + SV_HI + row * SRB + c4 * 8) = hh;
            *reinterpret_cast<uint2*>(sm + SV_LO + row * SRB + c4 * 8) = ll;
        }
        __syncthreads();

        // ---- dino stream ----
        compute_logits(sd, sb, DK_HI, DK_LO, lane, wq0);
        softmax_pv(sd, p, md0, md1, ld0, ld1, accd, sb, DV_HI, DV_LO, lane);

        // ---- sit stream ----
        compute_logits(p, sb, SK_HI, SK_LO, lane, wq0);

        // cosine stats on raw (scaled) logits
        #pragma unroll
        for (int tt = 0; tt < 8; tt++) {
            Sdd0 = fmaf(sd[tt][0], sd[tt][0], Sdd0); Sdd0 = fmaf(sd[tt][1], sd[tt][1], Sdd0);
            Sdd1 = fmaf(sd[tt][2], sd[tt][2], Sdd1); Sdd1 = fmaf(sd[tt][3], sd[tt][3], Sdd1);
            Sss0 = fmaf(p[tt][0], p[tt][0], Sss0);   Sss0 = fmaf(p[tt][1], p[tt][1], Sss0);
            Sss1 = fmaf(p[tt][2], p[tt][2], Sss1);   Sss1 = fmaf(p[tt][3], p[tt][3], Sss1);
            Ssd0 = fmaf(sd[tt][0], p[tt][0], Ssd0);  Ssd0 = fmaf(sd[tt][1], p[tt][1], Ssd0);
            Ssd1 = fmaf(sd[tt][2], p[tt][2], Ssd1);  Ssd1 = fmaf(sd[tt][3], p[tt][3], Ssd1);
        }

        softmax_pv(p, p, ms0, ms1, ls0, ls1, accs, sb, SV_HI, SV_LO, lane);
    }

    // ---- finalize ----
    const float EPS = 1e-12f;
    const int r = lane >> 2, cq = (lane & 3) * 2;
    const int n0r = q0 + wq0 + r;
    const float inv0 = 1.0f / ls0, inv1 = 1.0f / ls1;
    float* o0 = &g_attn[(size_t)(b * NN + n0r) * CC + h * HD];
    float* o1 = &g_attn[(size_t)(b * NN + n0r + 8) * CC + h * HD];
    #pragma unroll
    for (int tt = 0; tt < 9; tt++) {
        int col = tt * 8 + cq;
        float2 w0 = { accs[tt][0] * inv0, accs[tt][1] * inv0 };
        float2 w1 = { accs[tt][2] * inv1, accs[tt][3] * inv1 };
        *reinterpret_cast<float2*>(o0 + col) = w0;
        *reinterpret_cast<float2*>(o1 + col) = w1;
    }

    float dd0 = 0.f, ss0 = 0.f, xs0 = 0.f, dd1 = 0.f, ss1 = 0.f, xs1 = 0.f;
    #pragma unroll
    for (int tt = 0; tt < 9; tt++) {
        dd0 = fmaf(accd[tt][0], accd[tt][0], dd0); dd0 = fmaf(accd[tt][1], accd[tt][1], dd0);
        ss0 = fmaf(accs[tt][0], accs[tt][0], ss0); ss0 = fmaf(accs[tt][1], accs[tt][1], ss0);
        xs0 = fmaf(accd[tt][0], accs[tt][0], xs0); xs0 = fmaf(accd[tt][1], accs[tt][1], xs0);
        dd1 = fmaf(accd[tt][2], accd[tt][2], dd1); dd1 = fmaf(accd[tt][3], accd[tt][3], dd1);
        ss1 = fmaf(accs[tt][2], accs[tt][2], ss1); ss1 = fmaf(accs[tt][3], accs[tt][3], ss1);
        xs1 = fmaf(accd[tt][2], accs[tt][2], xs1); xs1 = fmaf(accd[tt][3], accs[tt][3], xs1);
    }
    #pragma unroll
    for (int o = 1; o <= 2; o <<= 1) {
        Sdd0 += __shfl_xor_sync(0xffffffffu, Sdd0, o);
        Sss0 += __shfl_xor_sync(0xffffffffu, Sss0, o);
        Ssd0 += __shfl_xor_sync(0xffffffffu, Ssd0, o);
        Sdd1 += __shfl_xor_sync(0xffffffffu, Sdd1, o);
        Sss1 += __shfl_xor_sync(0xffffffffu, Sss1, o);
        Ssd1 += __shfl_xor_sync(0xffffffffu, Ssd1, o);
        dd0 += __shfl_xor_sync(0xffffffffu, dd0, o);
        ss0 += __shfl_xor_sync(0xffffffffu, ss0, o);
        xs0 += __shfl_xor_sync(0xffffffffu, xs0, o);
        dd1 += __shfl_xor_sync(0xffffffffu, dd1, o);
        ss1 += __shfl_xor_sync(0xffffffffu, ss1, o);
        xs1 += __shfl_xor_sync(0xffffffffu, xs1, o);
    }
    if ((lane & 3) == 0) {
        float cosL0 = Ssd0 / (fmaxf(sqrtf(Sdd0), EPS) * fmaxf(sqrtf(Sss0), EPS));
        float cosL1 = Ssd1 / (fmaxf(sqrtf(Sdd1), EPS) * fmaxf(sqrtf(Sss1), EPS));
        float cosA0 = xs0 / (fmaxf(sqrtf(dd0), EPS) * fmaxf(sqrtf(ss0), EPS));
        float cosA1 = xs1 / (fmaxf(sqrtf(dd1), EPS) * fmaxf(sqrtf(ss1), EPS));
        g_cosL[bh * NN + n0r]     = cosL0;
        g_cosL[bh * NN + n0r + 8] = cosL1;
        g_cosA[bh * NN + n0r]     = cosA0;
        g_cosA[bh * NN + n0r + 8] = cosA1;
    }
}

// ---------------- deterministic loss reduction ----------------
__global__ __launch_bounds__(1024) void loss_kernel(float* __restrict__ out, int out_size)
{
    __shared__ float sL[1024], sA[1024];
    int t = threadIdx.x;
    float aL = 0.f, aA = 0.f;
    for (int i = t; i < NROWS; i += 1024) { aL += g_cosL[i]; aA += g_cosA[i]; }
    sL[t] = aL; sA[t] = aA;
    __syncthreads();
    for (int s = 512; s > 0; s >>= 1) {
        if (t < s) { sL[t] += sL[t + s]; sA[t] += sA[t + s]; }
        __syncthreads();
    }
    if (t == 0) {
        float meanL = sL[0] / (float)NROWS;
        float meanA = sA[0] / (float)NROWS;
        out[out_size - 1] = 1.5f - meanL - 0.5f * meanA;
    }
}

// ---------------- launch ----------------
extern "C" void kernel_launch(void* const* d_in, const int* in_sizes, int n_in,
                              void* d_out, int out_size)
{
    const float* x      = (const float*)d_in[0];
    const float* qkv_w  = (const float*)d_in[1];
    const float* qkv_b  = (const float*)d_in[2];
    const float* proj_w = (const float*)d_in[3];
    const float* proj_b = (const float*)d_in[4];
    const float* k_dino = (const float*)d_in[5];
    const float* v_dino = (const float*)d_in[6];
    float* out = (float*)d_out;

    float* qkvbuf  = nullptr;
    float* attnbuf = nullptr;
    cudaGetSymbolAddress((void**)&qkvbuf,  g_qkv);
    cudaGetSymbolAddress((void**)&attnbuf, g_attn);

    cudaFuncSetAttribute(gemm_mma_bias,  cudaFuncAttributeMaxDynamicSharedMemorySize, GEMM_SMEM);
    cudaFuncSetAttribute(attn_mma_kernel, cudaFuncAttributeMaxDynamicSharedMemorySize, ATTN_SMEM);

    // 1) qkv = x @ qkv_w^T + qkv_b
    {
        dim3 grid(C3 / TBN, (BB * NN) / TBM);
        gemm_mma_bias<<<grid, 256, GEMM_SMEM>>>(x, qkv_w, qkv_b, qkvbuf, BB * NN, C3, CC);
    }
    // 2) fused dual attention + alignment stats (tensor cores)
    {
        dim3 grid(NN / QB, BB * HH);
        attn_mma_kernel<<<grid, 256, ATTN_SMEM>>>(k_dino, v_dino);
    }
    // 3) out = attn @ proj_w^T + proj_b
    {
        dim3 grid(CC / TBN, (BB * NN) / TBM);
        gemm_mma_bias<<<grid, 256, GEMM_SMEM>>>(attnbuf, proj_w, proj_b, out, BB * NN, CC, CC);
    }
    // 4) distill loss
    loss_kernel<<<1, 1024>>>(out, out_size);
}

// round 6
// speedup vs baseline: 3.5492x; 1.0314x over previous
#include <cuda_runtime.h>
#include <cuda_bf16.h>
#include <math.h>
#include <cstdint>

// Problem constants
#define BB   2
#define NN   1024
#define CC   1152
#define HH   16
#define HD   72
#define C3   3456
#define NROWS (BB*HH*NN)

// ---------------- scratch (static device globals; no allocation) ----------------
static __device__ __nv_bfloat16 g_x_hi [BB*NN*CC],  g_x_lo [BB*NN*CC];
static __device__ __nv_bfloat16 g_w1_hi[C3*CC],     g_w1_lo[C3*CC];
static __device__ __nv_bfloat16 g_w2_hi[CC*CC],     g_w2_lo[CC*CC];
static __device__ __nv_bfloat16 g_kd_hi[BB*HH*NN*HD], g_kd_lo[BB*HH*NN*HD];
static __device__ __nv_bfloat16 g_vd_hi[BB*HH*NN*HD], g_vd_lo[BB*HH*NN*HD];
static __device__ __nv_bfloat16 g_qkv_hi[BB*NN*C3],   g_qkv_lo[BB*NN*C3];
static __device__ __nv_bfloat16 g_at_hi[BB*NN*CC],    g_at_lo[BB*NN*CC];
static __device__ float g_cosL[NROWS];
static __device__ float g_cosA[NROWS];

static __device__ __forceinline__ uint32_t smem_to_u32(const void* p) {
    uint32_t a;
    asm("{ .reg .u64 t; cvta.to.shared.u64 t, %1; cvt.u32.u64 %0, t; }" : "=r"(a) : "l"(p));
    return a;
}

// ---------------- primitives ----------------
static __device__ __forceinline__ void ldmatrix_x4(uint32_t addr, uint32_t& r0, uint32_t& r1, uint32_t& r2, uint32_t& r3) {
    asm volatile("ldmatrix.sync.aligned.m8n8.x4.shared.b16 {%0,%1,%2,%3}, [%4];"
                 : "=r"(r0), "=r"(r1), "=r"(r2), "=r"(r3) : "r"(addr));
}
static __device__ __forceinline__ void ldmatrix_x4_trans(uint32_t addr, uint32_t& r0, uint32_t& r1, uint32_t& r2, uint32_t& r3) {
    asm volatile("ldmatrix.sync.aligned.m8n8.x4.trans.shared.b16 {%0,%1,%2,%3}, [%4];"
                 : "=r"(r0), "=r"(r1), "=r"(r2), "=r"(r3) : "r"(addr));
}
static __device__ __forceinline__ void mma_bf16(float* d, const uint32_t* a, const uint32_t* b) {
    asm volatile("mma.sync.aligned.m16n8k16.row.col.f32.bf16.bf16.f32 "
                 "{%0,%1,%2,%3}, {%4,%5,%6,%7}, {%8,%9}, {%0,%1,%2,%3};"
                 : "+f"(d[0]), "+f"(d[1]), "+f"(d[2]), "+f"(d[3])
                 : "r"(a[0]), "r"(a[1]), "r"(a[2]), "r"(a[3]), "r"(b[0]), "r"(b[1]));
}
#define CP16(dst, src) asm volatile("cp.async.cg.shared.global [%0], [%1], 16;" :: "r"(dst), "l"(src))
#define CP_COMMIT()    asm volatile("cp.async.commit_group;" ::: "memory")
#define CP_WAIT0()     asm volatile("cp.async.wait_group 0;" ::: "memory")
#define CP_WAIT1()     asm volatile("cp.async.wait_group 1;" ::: "memory")

static __device__ __forceinline__ void cvt_hilo2(float a, float b, uint32_t& hi, uint32_t& lo)
{
    __nv_bfloat162 h = __floats2bfloat162_rn(a, b);
    float r0 = a - __low2float(h);
    float r1 = b - __high2float(h);
    __nv_bfloat162 l = __floats2bfloat162_rn(r0, r1);
    hi = *reinterpret_cast<uint32_t*>(&h);
    lo = *reinterpret_cast<uint32_t*>(&l);
}

// ---------------- prep: fp32 -> hi/lo bf16 ----------------
__global__ __launch_bounds__(256) void cvt_kernel(
    const float* __restrict__ src, __nv_bfloat16* __restrict__ hi,
    __nv_bfloat16* __restrict__ lo, int n4)
{
    int i = blockIdx.x * 256 + threadIdx.x;
    if (i < n4) {
        float4 v = reinterpret_cast<const float4*>(src)[i];
        uint2 h, l;
        cvt_hilo2(v.x, v.y, h.x, l.x);
        cvt_hilo2(v.z, v.w, h.y, l.y);
        reinterpret_cast<uint2*>(hi)[i] = h;
        reinterpret_cast<uint2*>(lo)[i] = l;
    }
}

// ---------------- bf16x3 NT GEMM: cp.async double-buffered, term-major ----------------
#define TBM 128
#define TBN 128
#define TKB 32
#define SKP 40                    // smem row stride in bf16 (80 bytes)
#define G_AH 0
#define G_AL 10240
#define G_BH 20480
#define G_BL 30720
#define G_STAGE 40960
#define GEMM_SMEM (2*G_STAGE)     // 81920

template<bool F32OUT>
__global__ __launch_bounds__(256, 2) void gemm_mma(
    const __nv_bfloat16* __restrict__ Ah, const __nv_bfloat16* __restrict__ Al,
    const __nv_bfloat16* __restrict__ Bh, const __nv_bfloat16* __restrict__ Bl,
    const float* __restrict__ bias, float* __restrict__ Cf,
    __nv_bfloat16* __restrict__ Ch, __nv_bfloat16* __restrict__ Cl,
    int M, int N, int K, int scale_limit, float scale)
{
    extern __shared__ char gsm[];
    const uint32_t u0 = smem_to_u32(gsm);

    const int tid  = threadIdx.x;
    const int lane = tid & 31;
    const int wid  = tid >> 5;
    const int wm   = wid & 3;
    const int wn   = wid >> 2;
    const int m0 = blockIdx.y * TBM;
    const int n0 = blockIdx.x * TBN;

    const int ar = lane & 15;
    const int ah = lane >> 4;
    const uint32_t aoff = (uint32_t)((wm * 32 + ar) * (SKP * 2) + ah * 16);
    const int br = (lane & 7) + ((lane >> 4) << 3);
    const int bh = (lane >> 3) & 1;
    const uint32_t boff = (uint32_t)((wn * 64 + br) * (SKP * 2) + bh * 16);

    // loader: per unrolled step u (0..7): mat = u>>1, row = (tid>>2)+64*(u&1), ch = tid&3
    const int lr = tid >> 2;
    const int lch = tid & 3;
    const char* srcb[4] = {
        (const char*)(Ah + (size_t)m0 * K), (const char*)(Al + (size_t)m0 * K),
        (const char*)(Bh + (size_t)n0 * K), (const char*)(Bl + (size_t)n0 * K) };

    float acc[2][8][4];
    #pragma unroll
    for (int i = 0; i < 2; i++)
        #pragma unroll
        for (int j = 0; j < 8; j++)
            #pragma unroll
            for (int q = 0; q < 4; q++) acc[i][j][q] = 0.f;

    const int nt = K / TKB;

    // prologue: stage 0
    #pragma unroll
    for (int u = 0; u < 8; u++) {
        const int mat = u >> 1;
        const int row = lr + (u & 1) * 64;
        CP16(u0 + (uint32_t)(mat * 10240 + row * 80 + lch * 16),
             srcb[mat] + ((size_t)row * K) * 2 + lch * 16);
    }
    CP_COMMIT();

    for (int t = 0; t < nt; t++) {
        if (t + 1 < nt) {
            const uint32_t nb = u0 + (uint32_t)(((t + 1) & 1) * G_STAGE);
            const int k0 = (t + 1) * TKB;
            #pragma unroll
            for (int u = 0; u < 8; u++) {
                const int mat = u >> 1;
                const int row = lr + (u & 1) * 64;
                CP16(nb + (uint32_t)(mat * 10240 + row * 80 + lch * 16),
                     srcb[mat] + ((size_t)row * K + k0) * 2 + lch * 16);
            }
            CP_COMMIT();
            CP_WAIT1();
        } else {
            CP_WAIT0();
        }
        __syncthreads();

        const uint32_t us = u0 + (uint32_t)((t & 1) * G_STAGE);
        #pragma unroll
        for (int ks = 0; ks < 2; ks++) {
            const uint32_t kso = ks * 32;
            uint32_t ahr[2][4], alr[2][4];
            #pragma unroll
            for (int i = 0; i < 2; i++) {
                uint32_t ad = aoff + (uint32_t)(i * 16 * SKP * 2) + kso;
                ldmatrix_x4(us + G_AH + ad, ahr[i][0], ahr[i][1], ahr[i][2], ahr[i][3]);
                ldmatrix_x4(us + G_AL + ad, alr[i][0], alr[i][1], alr[i][2], alr[i][3]);
            }
            uint32_t bhr[8][2], blr[8][2];
            #pragma unroll
            for (int g = 0; g < 4; g++) {
                uint32_t bd = boff + (uint32_t)(g * 16 * SKP * 2) + kso;
                uint32_t r0, r1, r2, r3;
                ldmatrix_x4(us + G_BH + bd, r0, r1, r2, r3);
                bhr[2*g][0] = r0; bhr[2*g][1] = r1; bhr[2*g+1][0] = r2; bhr[2*g+1][1] = r3;
                ldmatrix_x4(us + G_BL + bd, r0, r1, r2, r3);
                blr[2*g][0] = r0; blr[2*g][1] = r1; blr[2*g+1][0] = r2; blr[2*g+1][1] = r3;
            }
            #pragma unroll
            for (int i = 0; i < 2; i++)
                #pragma unroll
                for (int j = 0; j < 8; j++) mma_bf16(acc[i][j], ahr[i], bhr[j]);
            #pragma unroll
            for (int i = 0; i < 2; i++)
                #pragma unroll
                for (int j = 0; j < 8; j++) mma_bf16(acc[i][j], ahr[i], blr[j]);
            #pragma unroll
            for (int i = 0; i < 2; i++)
                #pragma unroll
                for (int j = 0; j < 8; j++) mma_bf16(acc[i][j], alr[i], bhr[j]);
        }
        __syncthreads();
    }

    const int cm = m0 + wm * 32 + (lane >> 2);
    const int cn = n0 + wn * 64 + (lane & 3) * 2;
    #pragma unroll
    for (int i = 0; i < 2; i++) {
        #pragma unroll
        for (int j = 0; j < 8; j++) {
            int nn = cn + j * 8;
            float2 b2 = *reinterpret_cast<const float2*>(bias + nn);
            float v00 = acc[i][j][0] + b2.x, v01 = acc[i][j][1] + b2.y;
            float v10 = acc[i][j][2] + b2.x, v11 = acc[i][j][3] + b2.y;
            if (nn < scale_limit) { v00 *= scale; v01 *= scale; v10 *= scale; v11 *= scale; }
            if (F32OUT) {
                float2 o0 = {v00, v01}, o1 = {v10, v11};
                *reinterpret_cast<float2*>(Cf + (size_t)(cm + i * 16    ) * N + nn) = o0;
                *reinterpret_cast<float2*>(Cf + (size_t)(cm + i * 16 + 8) * N + nn) = o1;
            } else {
                uint32_t h, l;
                size_t idx0 = ((size_t)(cm + i * 16) * N + nn) >> 1;
                size_t idx1 = ((size_t)(cm + i * 16 + 8) * N + nn) >> 1;
                cvt_hilo2(v00, v01, h, l);
                reinterpret_cast<uint32_t*>(Ch)[idx0] = h;
                reinterpret_cast<uint32_t*>(Cl)[idx0] = l;
                cvt_hilo2(v10, v11, h, l);
                reinterpret_cast<uint32_t*>(Ch)[idx1] = h;
                reinterpret_cast<uint32_t*>(Cl)[idx1] = l;
            }
        }
    }
}

// =====================================================================
// Fused dual attention via mma.sync (flash-style, bf16x3, cp.async loads)
// =====================================================================
#define QB  128
#define KT  64
#define SRB 176
#define AQ_HI 0
#define AQ_LO (QB*SRB)
#define DK_HI (2*QB*SRB)
#define DK_LO (DK_HI + KT*SRB)
#define DV_HI (DK_LO + KT*SRB)
#define DV_LO (DV_HI + KT*SRB)
#define SK_HI (DV_LO + KT*SRB)
#define SK_LO (SK_HI + KT*SRB)
#define SV_HI (SK_LO + KT*SRB)
#define SV_LO (SV_HI + KT*SRB)
#define ATTN_SMEM (SV_LO + KT*SRB)   // 135168

static __device__ __forceinline__ void cp_tile64(uint32_t dst, const char* src, int sstride, int tid) {
    for (int i = tid; i < 64 * 9; i += 256) {
        int r = i / 9, ch = i - r * 9;
        CP16(dst + (uint32_t)(r * SRB + ch * 16), src + (size_t)r * sstride + ch * 16);
    }
}

static __device__ __forceinline__ void compute_logits(
    float s[8][4], uint32_t sb, uint32_t khi_off, uint32_t klo_off, int lane, int wq0)
{
    #pragma unroll
    for (int tt = 0; tt < 8; tt++)
        #pragma unroll
        for (int q = 0; q < 4; q++) s[tt][q] = 0.f;

    const uint32_t qaddr = sb + (uint32_t)((wq0 + (lane & 15)) * SRB + (lane >> 4) * 16);
    const int ksub = lane >> 3, ki = lane & 7;
    const uint32_t kn_row = (uint32_t)(((ksub >> 1) << 3) + ki);
    const uint32_t kk_half = (uint32_t)((ksub & 1) * 16);

    #pragma unroll
    for (int ks = 0; ks < 5; ks++) {
        uint32_t ahr[4], alr[4];
        ldmatrix_x4(qaddr + AQ_HI + ks * 32, ahr[0], ahr[1], ahr[2], ahr[3]);
        ldmatrix_x4(qaddr + AQ_LO + ks * 32, alr[0], alr[1], alr[2], alr[3]);
        uint32_t bh_[8][2], bl_[8][2];
        #pragma unroll
        for (int g = 0; g < 4; g++) {
            uint32_t kaddr = sb + (uint32_t)((g * 16 + kn_row) * SRB + ks * 32) + kk_half;
            uint32_t r0, r1, r2, r3;
            ldmatrix_x4(kaddr + khi_off, r0, r1, r2, r3);
            bh_[2*g][0] = r0; bh_[2*g][1] = r1; bh_[2*g+1][0] = r2; bh_[2*g+1][1] = r3;
            ldmatrix_x4(kaddr + klo_off, r0, r1, r2, r3);
            bl_[2*g][0] = r0; bl_[2*g][1] = r1; bl_[2*g+1][0] = r2; bl_[2*g+1][1] = r3;
        }
        #pragma unroll
        for (int tt = 0; tt < 8; tt++) mma_bf16(s[tt], ahr, bh_[tt]);
        #pragma unroll
        for (int tt = 0; tt < 8; tt++) mma_bf16(s[tt], ahr, bl_[tt]);
        #pragma unroll
        for (int tt = 0; tt < 8; tt++) mma_bf16(s[tt], alr, bh_[tt]);
    }
}

static __device__ __forceinline__ void softmax_pv(
    const float s[8][4], float p[8][4],
    float& m0, float& m1, float& l0, float& l1,
    float acc[9][4],
    uint32_t sb, uint32_t vhi_off, uint32_t vlo_off, int lane)
{
    float mx0 = -1e30f, mx1 = -1e30f;
    #pragma unroll
    for (int tt = 0; tt < 8; tt++) {
        mx0 = fmaxf(mx0, fmaxf(s[tt][0], s[tt][1]));
        mx1 = fmaxf(mx1, fmaxf(s[tt][2], s[tt][3]));
    }
    mx0 = fmaxf(mx0, __shfl_xor_sync(0xffffffffu, mx0, 1));
    mx0 = fmaxf(mx0, __shfl_xor_sync(0xffffffffu, mx0, 2));
    mx1 = fmaxf(mx1, __shfl_xor_sync(0xffffffffu, mx1, 1));
    mx1 = fmaxf(mx1, __shfl_xor_sync(0xffffffffu, mx1, 2));

    const float m0n = fmaxf(m0, mx0), m1n = fmaxf(m1, mx1);
    const float c0 = __expf(m0 - m0n), c1 = __expf(m1 - m1n);
    m0 = m0n; m1 = m1n;

    float r0 = 0.f, r1 = 0.f;
    #pragma unroll
    for (int tt = 0; tt < 8; tt++) {
        float p0 = __expf(s[tt][0] - m0n), p1 = __expf(s[tt][1] - m0n);
        float p2 = __expf(s[tt][2] - m1n), p3 = __expf(s[tt][3] - m1n);
        p[tt][0] = p0; p[tt][1] = p1; p[tt][2] = p2; p[tt][3] = p3;
        r0 += p0 + p1; r1 += p2 + p3;
    }
    r0 += __shfl_xor_sync(0xffffffffu, r0, 1);
    r0 += __shfl_xor_sync(0xffffffffu, r0, 2);
    r1 += __shfl_xor_sync(0xffffffffu, r1, 1);
    r1 += __shfl_xor_sync(0xffffffffu, r1, 2);
    l0 = l0 * c0 + r0;
    l1 = l1 * c1 + r1;

    #pragma unroll
    for (int tt = 0; tt < 9; tt++) {
        acc[tt][0] *= c0; acc[tt][1] *= c0;
        acc[tt][2] *= c1; acc[tt][3] *= c1;
    }

    const int vsub = lane >> 3, vi = lane & 7;
    #pragma unroll
    for (int j = 0; j < 4; j++) {
        uint32_t ahi[4], alo[4];
        cvt_hilo2(p[2*j][0],     p[2*j][1],     ahi[0], alo[0]);
        cvt_hilo2(p[2*j][2],     p[2*j][3],     ahi[1], alo[1]);
        cvt_hilo2(p[2*j + 1][0], p[2*j + 1][1], ahi[2], alo[2]);
        cvt_hilo2(p[2*j + 1][2], p[2*j + 1][3], ahi[3], alo[3]);
        const uint32_t krow = (uint32_t)(16 * j + vi + (vsub & 1) * 8);
        const uint32_t vrowa = sb + krow * SRB + (uint32_t)((vsub >> 1) * 16);
        #pragma unroll
        for (int dpp = 0; dpp < 2; dpp++) {
            uint32_t va0 = vrowa + (uint32_t)(2 * dpp * 32);
            uint32_t va1 = va0 + 32;
            uint32_t vh0[4], vl0[4], vh1[4], vl1[4];
            ldmatrix_x4_trans(va0 + vhi_off, vh0[0], vh0[1], vh0[2], vh0[3]);
            ldmatrix_x4_trans(va0 + vlo_off, vl0[0], vl0[1], vl0[2], vl0[3]);
            ldmatrix_x4_trans(va1 + vhi_off, vh1[0], vh1[1], vh1[2], vh1[3]);
            ldmatrix_x4_trans(va1 + vlo_off, vl1[0], vl1[1], vl1[2], vl1[3]);
            float* a0 = acc[4*dpp+0]; float* a1 = acc[4*dpp+1];
            float* a2 = acc[4*dpp+2]; float* a3 = acc[4*dpp+3];
            mma_bf16(a0, ahi, vh0); mma_bf16(a1, ahi, vh0 + 2);
            mma_bf16(a2, ahi, vh1); mma_bf16(a3, ahi, vh1 + 2);
            mma_bf16(a0, ahi, vl0); mma_bf16(a1, ahi, vl0 + 2);
            mma_bf16(a2, ahi, vl1); mma_bf16(a3, ahi, vl1 + 2);
            mma_bf16(a0, alo, vh0); mma_bf16(a1, alo, vh0 + 2);
            mma_bf16(a2, alo, vh1); mma_bf16(a3, alo, vh1 + 2);
        }
        {
            uint32_t va = vrowa + 128;
            uint32_t vh[4], vl[4];
            ldmatrix_x4_trans(va + vhi_off, vh[0], vh[1], vh[2], vh[3]);
            ldmatrix_x4_trans(va + vlo_off, vl[0], vl[1], vl[2], vl[3]);
            mma_bf16(acc[8], ahi, vh);
            mma_bf16(acc[8], ahi, vl);
            mma_bf16(acc[8], alo, vh);
        }
    }
}

__global__ __launch_bounds__(256) void attn_mma_kernel()
{
    extern __shared__ char sm[];
    const uint32_t sb = smem_to_u32(sm);
    const int tid = threadIdx.x, lane = tid & 31, wid = tid >> 5;
    const int bh = blockIdx.y, b = bh >> 4, h = bh & 15;
    const int q0 = blockIdx.x * QB;
    const int wq0 = wid * 16;

    // zero pads (bytes 144..159 of each row)
    for (int r = tid; r < 2 * QB + 8 * KT; r += 256)
        *reinterpret_cast<uint4*>(sm + (size_t)r * SRB + 144) = make_uint4(0, 0, 0, 0);

    // stage Q hi/lo via cp.async (already scaled by GEMM1 epilogue)
    {
        const char* qh = (const char*)g_qkv_hi + ((size_t)(b * NN + q0) * C3 + h * HD) * 2;
        const char* ql = (const char*)g_qkv_lo + ((size_t)(b * NN + q0) * C3 + h * HD) * 2;
        for (int i = tid; i < QB * 9; i += 256) {
            int r = i / 9, ch = i - r * 9;
            CP16(sb + AQ_HI + (uint32_t)(r * SRB + ch * 16), qh + (size_t)r * (C3 * 2) + ch * 16);
            CP16(sb + AQ_LO + (uint32_t)(r * SRB + ch * 16), ql + (size_t)r * (C3 * 2) + ch * 16);
        }
        CP_COMMIT();
    }

    float accd[9][4], accs[9][4];
    #pragma unroll
    for (int tt = 0; tt < 9; tt++)
        #pragma unroll
        for (int q = 0; q < 4; q++) { accd[tt][q] = 0.f; accs[tt][q] = 0.f; }
    float md0 = -1e30f, md1 = -1e30f, ms0 = -1e30f, ms1 = -1e30f;
    float ld0 = 0.f, ld1 = 0.f, ls0 = 0.f, ls1 = 0.f;
    float Sdd0 = 0.f, Sdd1 = 0.f, Sss0 = 0.f, Sss1 = 0.f, Ssd0 = 0.f, Ssd1 = 0.f;

    float sd[8][4], p[8][4];

    for (int t = 0; t < NN / KT; t++) {
        const int k0 = t * KT;

        __syncthreads();   // previous tile fully consumed
        {
            size_t dbase = ((size_t)(bh * NN + k0) * HD) * 2;
            cp_tile64(sb + DK_HI, (const char*)g_kd_hi + dbase, HD * 2, tid);
            cp_tile64(sb + DK_LO, (const char*)g_kd_lo + dbase, HD * 2, tid);
            cp_tile64(sb + DV_HI, (const char*)g_vd_hi + dbase, HD * 2, tid);
            cp_tile64(sb + DV_LO, (const char*)g_vd_lo + dbase, HD * 2, tid);
            size_t kb = ((size_t)(b * NN + k0) * C3 + CC + h * HD) * 2;
            size_t vb = ((size_t)(b * NN + k0) * C3 + 2 * CC + h * HD) * 2;
            cp_tile64(sb + SK_HI, (const char*)g_qkv_hi + kb, C3 * 2, tid);
            cp_tile64(sb + SK_LO, (const char*)g_qkv_lo + kb, C3 * 2, tid);
            cp_tile64(sb + SV_HI, (const char*)g_qkv_hi + vb, C3 * 2, tid);
            cp_tile64(sb + SV_LO, (const char*)g_qkv_lo + vb, C3 * 2, tid);
            CP_COMMIT();
        }
        CP_WAIT0();
        __syncthreads();

        // ---- dino stream ----
        compute_logits(sd, sb, DK_HI, DK_LO, lane, wq0);
        softmax_pv(sd, p, md0, md1, ld0, ld1, accd, sb, DV_HI, DV_LO, lane);

        // ---- sit stream ----
        compute_logits(p, sb, SK_HI, SK_LO, lane, wq0);

        #pragma unroll
        for (int tt = 0; tt < 8; tt++) {
            Sdd0 = fmaf(sd[tt][0], sd[tt][0], Sdd0); Sdd0 = fmaf(sd[tt][1], sd[tt][1], Sdd0);
            Sdd1 = fmaf(sd[tt][2], sd[tt][2], Sdd1); Sdd1 = fmaf(sd[tt][3], sd[tt][3], Sdd1);
            Sss0 = fmaf(p[tt][0], p[tt][0], Sss0);   Sss0 = fmaf(p[tt][1], p[tt][1], Sss0);
            Sss1 = fmaf(p[tt][2], p[tt][2], Sss1);   Sss1 = fmaf(p[tt][3], p[tt][3], Sss1);
            Ssd0 = fmaf(sd[tt][0], p[tt][0], Ssd0);  Ssd0 = fmaf(sd[tt][1], p[tt][1], Ssd0);
            Ssd1 = fmaf(sd[tt][2], p[tt][2], Ssd1);  Ssd1 = fmaf(sd[tt][3], p[tt][3], Ssd1);
        }

        softmax_pv(p, p, ms0, ms1, ls0, ls1, accs, sb, SV_HI, SV_LO, lane);
    }

    // ---- finalize ----
    const float EPS = 1e-12f;
    const int r = lane >> 2, cq = (lane & 3) * 2;
    const int n0r = q0 + wq0 + r;
    const float inv0 = 1.0f / ls0, inv1 = 1.0f / ls1;
    uint32_t* oh = reinterpret_cast<uint32_t*>(g_at_hi);
    uint32_t* ol = reinterpret_cast<uint32_t*>(g_at_lo);
    #pragma unroll
    for (int tt = 0; tt < 9; tt++) {
        int col = tt * 8 + cq;
        size_t i0 = ((size_t)(b * NN + n0r) * CC + h * HD + col) >> 1;
        size_t i1 = ((size_t)(b * NN + n0r + 8) * CC + h * HD + col) >> 1;
        uint32_t hh, ll;
        cvt_hilo2(accs[tt][0] * inv0, accs[tt][1] * inv0, hh, ll);
        oh[i0] = hh; ol[i0] = ll;
        cvt_hilo2(accs[tt][2] * inv1, accs[tt][3] * inv1, hh, ll);
        oh[i1] = hh; ol[i1] = ll;
    }

    float dd0 = 0.f, ss0 = 0.f, xs0 = 0.f, dd1 = 0.f, ss1 = 0.f, xs1 = 0.f;
    #pragma unroll
    for (int tt = 0; tt < 9; tt++) {
        dd0 = fmaf(accd[tt][0], accd[tt][0], dd0); dd0 = fmaf(accd[tt][1], accd[tt][1], dd0);
        ss0 = fmaf(accs[tt][0], accs[tt][0], ss0); ss0 = fmaf(accs[tt][1], accs[tt][1], ss0);
        xs0 = fmaf(accd[tt][0], accs[tt][0], xs0); xs0 = fmaf(accd[tt][1], accs[tt][1], xs0);
        dd1 = fmaf(accd[tt][2], accd[tt][2], dd1); dd1 = fmaf(accd[tt][3], accd[tt][3], dd1);
        ss1 = fmaf(accs[tt][2], accs[tt][2], ss1); ss1 = fmaf(accs[tt][3], accs[tt][3], ss1);
        xs1 = fmaf(accd[tt][2], accs[tt][2], xs1); xs1 = fmaf(accd[tt][3], accs[tt][3], xs1);
    }
    #pragma unroll
    for (int o = 1; o <= 2; o <<= 1) {
        Sdd0 += __shfl_xor_sync(0xffffffffu, Sdd0, o);
        Sss0 += __shfl_xor_sync(0xffffffffu, Sss0, o);
        Ssd0 += __shfl_xor_sync(0xffffffffu, Ssd0, o);
        Sdd1 += __shfl_xor_sync(0xffffffffu, Sdd1, o);
        Sss1 += __shfl_xor_sync(0xffffffffu, Sss1, o);
        Ssd1 += __shfl_xor_sync(0xffffffffu, Ssd1, o);
        dd0 += __shfl_xor_sync(0xffffffffu, dd0, o);
        ss0 += __shfl_xor_sync(0xffffffffu, ss0, o);
        xs0 += __shfl_xor_sync(0xffffffffu, xs0, o);
        dd1 += __shfl_xor_sync(0xffffffffu, dd1, o);
        ss1 += __shfl_xor_sync(0xffffffffu, ss1, o);
        xs1 += __shfl_xor_sync(0xffffffffu, xs1, o);
    }
    if ((lane & 3) == 0) {
        float cosL0 = Ssd0 / (fmaxf(sqrtf(Sdd0), EPS) * fmaxf(sqrtf(Sss0), EPS));
        float cosL1 = Ssd1 / (fmaxf(sqrtf(Sdd1), EPS) * fmaxf(sqrtf(Sss1), EPS));
        float cosA0 = xs0 / (fmaxf(sqrtf(dd0), EPS) * fmaxf(sqrtf(ss0), EPS));
        float cosA1 = xs1 / (fmaxf(sqrtf(dd1), EPS) * fmaxf(sqrtf(ss1), EPS));
        g_cosL[bh * NN + n0r]     = cosL0;
        g_cosL[bh * NN + n0r + 8] = cosL1;
        g_cosA[bh * NN + n0r]     = cosA0;
        g_cosA[bh * NN + n0r + 8] = cosA1;
    }
}

// ---------------- deterministic loss reduction ----------------
__global__ __launch_bounds__(1024) void loss_kernel(float* __restrict__ out, int out_size)
{
    __shared__ float sL[1024], sA[1024];
    int t = threadIdx.x;
    float aL = 0.f, aA = 0.f;
    for (int i = t; i < NROWS; i += 1024) { aL += g_cosL[i]; aA += g_cosA[i]; }
    sL[t] = aL; sA[t] = aA;
    __syncthreads();
    for (int s = 512; s > 0; s >>= 1) {
        if (t < s) { sL[t] += sL[t + s]; sA[t] += sA[t + s]; }
        __syncthreads();
    }
    if (t == 0) {
        float meanL = sL[0] / (float)NROWS;
        float meanA = sA[0] / (float)NROWS;
        out[out_size - 1] = 1.5f - meanL - 0.5f * meanA;
    }
}

// ---------------- launch ----------------
extern "C" void kernel_launch(void* const* d_in, const int* in_sizes, int n_in,
                              void* d_out, int out_size)
{
    const float* x      = (const float*)d_in[0];
    const float* qkv_w  = (const float*)d_in[1];
    const float* qkv_b  = (const float*)d_in[2];
    const float* proj_w = (const float*)d_in[3];
    const float* proj_b = (const float*)d_in[4];
    const float* k_dino = (const float*)d_in[5];
    const float* v_dino = (const float*)d_in[6];
    float* out = (float*)d_out;

    const float scale = 0.11785113019775793f;   // 1/sqrt(72)

    __nv_bfloat16 *xh, *xl, *w1h, *w1l, *w2h, *w2l, *kdh, *kdl, *vdh, *vdl;
    __nv_bfloat16 *qh, *ql, *ath, *atl;
    cudaGetSymbolAddress((void**)&xh,  g_x_hi);  cudaGetSymbolAddress((void**)&xl,  g_x_lo);
    cudaGetSymbolAddress((void**)&w1h, g_w1_hi); cudaGetSymbolAddress((void**)&w1l, g_w1_lo);
    cudaGetSymbolAddress((void**)&w2h, g_w2_hi); cudaGetSymbolAddress((void**)&w2l, g_w2_lo);
    cudaGetSymbolAddress((void**)&kdh, g_kd_hi); cudaGetSymbolAddress((void**)&kdl, g_kd_lo);
    cudaGetSymbolAddress((void**)&vdh, g_vd_hi); cudaGetSymbolAddress((void**)&vdl, g_vd_lo);
    cudaGetSymbolAddress((void**)&qh,  g_qkv_hi); cudaGetSymbolAddress((void**)&ql,  g_qkv_lo);
    cudaGetSymbolAddress((void**)&ath, g_at_hi);  cudaGetSymbolAddress((void**)&atl, g_at_lo);

    cudaFuncSetAttribute(gemm_mma<false>, cudaFuncAttributeMaxDynamicSharedMemorySize, GEMM_SMEM);
    cudaFuncSetAttribute(gemm_mma<true>,  cudaFuncAttributeMaxDynamicSharedMemorySize, GEMM_SMEM);
    cudaFuncSetAttribute(attn_mma_kernel, cudaFuncAttributeMaxDynamicSharedMemorySize, ATTN_SMEM);

    // 0) prep conversions
    {
        int n4;
        n4 = BB*NN*CC/4;    cvt_kernel<<<(n4+255)/256, 256>>>(x,      xh,  xl,  n4);
        n4 = C3*CC/4;       cvt_kernel<<<(n4+255)/256, 256>>>(qkv_w,  w1h, w1l, n4);
        n4 = CC*CC/4;       cvt_kernel<<<(n4+255)/256, 256>>>(proj_w, w2h, w2l, n4);
        n4 = BB*HH*NN*HD/4; cvt_kernel<<<(n4+255)/256, 256>>>(k_dino, kdh, kdl, n4);
        n4 = BB*HH*NN*HD/4; cvt_kernel<<<(n4+255)/256, 256>>>(v_dino, vdh, vdl, n4);
    }
    // 1) qkv = x @ qkv_w^T + qkv_b  (bf16 hi/lo out; Q cols prescaled)
    {
        dim3 grid(C3 / TBN, (BB * NN) / TBM);
        gemm_mma<false><<<grid, 256, GEMM_SMEM>>>(xh, xl, w1h, w1l, qkv_b,
                                                  nullptr, qh, ql,
                                                  BB * NN, C3, CC, CC, scale);
    }
    // 2) fused dual attention + alignment stats
    {
        dim3 grid(NN / QB, BB * HH);
        attn_mma_kernel<<<grid, 256, ATTN_SMEM>>>();
    }
    // 3) out = attn @ proj_w^T + proj_b  (f32 out)
    {
        dim3 grid(CC / TBN, (BB * NN) / TBM);
        gemm_mma<true><<<grid, 256, GEMM_SMEM>>>(ath, atl, w2h, w2l, proj_b,
                                                 out, nullptr, nullptr,
                                                 BB * NN, CC, CC, 0, 1.0f);
    }
    // 4) distill loss
    loss_kernel<<<1, 1024>>>(out, out_size);
}

// round 7
// speedup vs baseline: 3.7550x; 1.0580x over previous
#include <cuda_runtime.h>
#include <cuda_bf16.h>
#include <math.h>
#include <cstdint>

// Problem constants
#define BB   2
#define NN   1024
#define CC   1152
#define HH   16
#define HD   72
#define C3   3456
#define NROWS (BB*HH*NN)

// ---------------- scratch (static device globals; no allocation) ----------------
static __device__ __nv_bfloat16 g_x_hi [BB*NN*CC],  g_x_lo [BB*NN*CC];
static __device__ __nv_bfloat16 g_w1_hi[C3*CC],     g_w1_lo[C3*CC];
static __device__ __nv_bfloat16 g_w2_hi[CC*CC],     g_w2_lo[CC*CC];
static __device__ __nv_bfloat16 g_kd_hi[BB*HH*NN*HD], g_kd_lo[BB*HH*NN*HD];
static __device__ __nv_bfloat16 g_vd_hi[BB*HH*NN*HD], g_vd_lo[BB*HH*NN*HD];
static __device__ __nv_bfloat16 g_qkv_hi[BB*NN*C3],   g_qkv_lo[BB*NN*C3];
static __device__ __nv_bfloat16 g_at_hi[BB*NN*CC],    g_at_lo[BB*NN*CC];
static __device__ float g_cosL[NROWS];
static __device__ float g_cosA[NROWS];

static __device__ __forceinline__ uint32_t smem_to_u32(const void* p) {
    uint32_t a;
    asm("{ .reg .u64 t; cvta.to.shared.u64 t, %1; cvt.u32.u64 %0, t; }" : "=r"(a) : "l"(p));
    return a;
}

// ---------------- primitives ----------------
static __device__ __forceinline__ void ldmatrix_x4(uint32_t addr, uint32_t& r0, uint32_t& r1, uint32_t& r2, uint32_t& r3) {
    asm volatile("ldmatrix.sync.aligned.m8n8.x4.shared.b16 {%0,%1,%2,%3}, [%4];"
                 : "=r"(r0), "=r"(r1), "=r"(r2), "=r"(r3) : "r"(addr));
}
static __device__ __forceinline__ void ldmatrix_x4_trans(uint32_t addr, uint32_t& r0, uint32_t& r1, uint32_t& r2, uint32_t& r3) {
    asm volatile("ldmatrix.sync.aligned.m8n8.x4.trans.shared.b16 {%0,%1,%2,%3}, [%4];"
                 : "=r"(r0), "=r"(r1), "=r"(r2), "=r"(r3) : "r"(addr));
}
static __device__ __forceinline__ void mma_bf16(float* d, const uint32_t* a, const uint32_t* b) {
    asm volatile("mma.sync.aligned.m16n8k16.row.col.f32.bf16.bf16.f32 "
                 "{%0,%1,%2,%3}, {%4,%5,%6,%7}, {%8,%9}, {%0,%1,%2,%3};"
                 : "+f"(d[0]), "+f"(d[1]), "+f"(d[2]), "+f"(d[3])
                 : "r"(a[0]), "r"(a[1]), "r"(a[2]), "r"(a[3]), "r"(b[0]), "r"(b[1]));
}
#define CP16(dst, src) asm volatile("cp.async.cg.shared.global [%0], [%1], 16;" :: "r"(dst), "l"(src))
#define CP_COMMIT()    asm volatile("cp.async.commit_group;" ::: "memory")
#define CP_WAIT0()     asm volatile("cp.async.wait_group 0;" ::: "memory")
#define CP_WAIT1()     asm volatile("cp.async.wait_group 1;" ::: "memory")

static __device__ __forceinline__ void cvt_hilo2(float a, float b, uint32_t& hi, uint32_t& lo)
{
    __nv_bfloat162 h = __floats2bfloat162_rn(a, b);
    float r0 = a - __low2float(h);
    float r1 = b - __high2float(h);
    __nv_bfloat162 l = __floats2bfloat162_rn(r0, r1);
    hi = *reinterpret_cast<uint32_t*>(&h);
    lo = *reinterpret_cast<uint32_t*>(&l);
}

// ---------------- fused prep: fp32 -> hi/lo bf16, 5 tensors, one launch ----------------
#define N1 (BB*NN*CC/4)
#define N2 (C3*CC/4)
#define N3 (CC*CC/4)
#define N4 (BB*HH*NN*HD/4)
#define N5 (BB*HH*NN*HD/4)
#define O2 (N1)
#define O3 (O2+N2)
#define O4 (O3+N3)
#define O5 (O4+N4)
#define NTOT (O5+N5)

static __device__ __forceinline__ void cvt4(const float* src, __nv_bfloat16* hi, __nv_bfloat16* lo, int i) {
    float4 v = reinterpret_cast<const float4*>(src)[i];
    uint2 h, l;
    cvt_hilo2(v.x, v.y, h.x, l.x);
    cvt_hilo2(v.z, v.w, h.y, l.y);
    reinterpret_cast<uint2*>(hi)[i] = h;
    reinterpret_cast<uint2*>(lo)[i] = l;
}

__global__ __launch_bounds__(256) void cvt_all_kernel(
    const float* __restrict__ x, const float* __restrict__ w1, const float* __restrict__ w2,
    const float* __restrict__ kd, const float* __restrict__ vd)
{
    int i = blockIdx.x * 256 + threadIdx.x;
    if (i < O2)            cvt4(x,  g_x_hi,  g_x_lo,  i);
    else if (i < O3)       cvt4(w1, g_w1_hi, g_w1_lo, i - O2);
    else if (i < O4)       cvt4(w2, g_w2_hi, g_w2_lo, i - O3);
    else if (i < O5)       cvt4(kd, g_kd_hi, g_kd_lo, i - O4);
    else if (i < NTOT)     cvt4(vd, g_vd_hi, g_vd_lo, i - O5);
}

// ---------------- bf16x3 NT GEMM: cp.async double-buffered, term-major ----------------
#define TBM 128
#define TBN 128
#define TKB 32
#define SKP 40
#define G_AH 0
#define G_AL 10240
#define G_BH 20480
#define G_BL 30720
#define G_STAGE 40960
#define GEMM_SMEM (2*G_STAGE)

template<bool F32OUT>
__global__ __launch_bounds__(256, 2) void gemm_mma(
    const __nv_bfloat16* __restrict__ Ah, const __nv_bfloat16* __restrict__ Al,
    const __nv_bfloat16* __restrict__ Bh, const __nv_bfloat16* __restrict__ Bl,
    const float* __restrict__ bias, float* __restrict__ Cf,
    __nv_bfloat16* __restrict__ Ch, __nv_bfloat16* __restrict__ Cl,
    int M, int N, int K, int scale_limit, float scale)
{
    extern __shared__ char gsm[];
    const uint32_t u0 = smem_to_u32(gsm);

    const int tid  = threadIdx.x;
    const int lane = tid & 31;
    const int wid  = tid >> 5;
    const int wm   = wid & 3;
    const int wn   = wid >> 2;
    const int m0 = blockIdx.y * TBM;
    const int n0 = blockIdx.x * TBN;

    const int ar = lane & 15;
    const int ah = lane >> 4;
    const uint32_t aoff = (uint32_t)((wm * 32 + ar) * (SKP * 2) + ah * 16);
    const int br = (lane & 7) + ((lane >> 4) << 3);
    const int bh = (lane >> 3) & 1;
    const uint32_t boff = (uint32_t)((wn * 64 + br) * (SKP * 2) + bh * 16);

    const int lr = tid >> 2;
    const int lch = tid & 3;
    const char* srcb[4] = {
        (const char*)(Ah + (size_t)m0 * K), (const char*)(Al + (size_t)m0 * K),
        (const char*)(Bh + (size_t)n0 * K), (const char*)(Bl + (size_t)n0 * K) };

    float acc[2][8][4];
    #pragma unroll
    for (int i = 0; i < 2; i++)
        #pragma unroll
        for (int j = 0; j < 8; j++)
            #pragma unroll
            for (int q = 0; q < 4; q++) acc[i][j][q] = 0.f;

    const int nt = K / TKB;

    #pragma unroll
    for (int u = 0; u < 8; u++) {
        const int mat = u >> 1;
        const int row = lr + (u & 1) * 64;
        CP16(u0 + (uint32_t)(mat * 10240 + row * 80 + lch * 16),
             srcb[mat] + ((size_t)row * K) * 2 + lch * 16);
    }
    CP_COMMIT();

    for (int t = 0; t < nt; t++) {
        if (t + 1 < nt) {
            const uint32_t nb = u0 + (uint32_t)(((t + 1) & 1) * G_STAGE);
            const int k0 = (t + 1) * TKB;
            #pragma unroll
            for (int u = 0; u < 8; u++) {
                const int mat = u >> 1;
                const int row = lr + (u & 1) * 64;
                CP16(nb + (uint32_t)(mat * 10240 + row * 80 + lch * 16),
                     srcb[mat] + ((size_t)row * K + k0) * 2 + lch * 16);
            }
            CP_COMMIT();
            CP_WAIT1();
        } else {
            CP_WAIT0();
        }
        __syncthreads();

        const uint32_t us = u0 + (uint32_t)((t & 1) * G_STAGE);
        #pragma unroll
        for (int ks = 0; ks < 2; ks++) {
            const uint32_t kso = ks * 32;
            uint32_t ahr[2][4], alr[2][4];
            #pragma unroll
            for (int i = 0; i < 2; i++) {
                uint32_t ad = aoff + (uint32_t)(i * 16 * SKP * 2) + kso;
                ldmatrix_x4(us + G_AH + ad, ahr[i][0], ahr[i][1], ahr[i][2], ahr[i][3]);
                ldmatrix_x4(us + G_AL + ad, alr[i][0], alr[i][1], alr[i][2], alr[i][3]);
            }
            uint32_t bhr[8][2], blr[8][2];
            #pragma unroll
            for (int g = 0; g < 4; g++) {
                uint32_t bd = boff + (uint32_t)(g * 16 * SKP * 2) + kso;
                uint32_t r0, r1, r2, r3;
                ldmatrix_x4(us + G_BH + bd, r0, r1, r2, r3);
                bhr[2*g][0] = r0; bhr[2*g][1] = r1; bhr[2*g+1][0] = r2; bhr[2*g+1][1] = r3;
                ldmatrix_x4(us + G_BL + bd, r0, r1, r2, r3);
                blr[2*g][0] = r0; blr[2*g][1] = r1; blr[2*g+1][0] = r2; blr[2*g+1][1] = r3;
            }
            #pragma unroll
            for (int i = 0; i < 2; i++)
                #pragma unroll
                for (int j = 0; j < 8; j++) mma_bf16(acc[i][j], ahr[i], bhr[j]);
            #pragma unroll
            for (int i = 0; i < 2; i++)
                #pragma unroll
                for (int j = 0; j < 8; j++) mma_bf16(acc[i][j], ahr[i], blr[j]);
            #pragma unroll
            for (int i = 0; i < 2; i++)
                #pragma unroll
                for (int j = 0; j < 8; j++) mma_bf16(acc[i][j], alr[i], bhr[j]);
        }
        __syncthreads();
    }

    const int cm = m0 + wm * 32 + (lane >> 2);
    const int cn = n0 + wn * 64 + (lane & 3) * 2;
    #pragma unroll
    for (int i = 0; i < 2; i++) {
        #pragma unroll
        for (int j = 0; j < 8; j++) {
            int nn = cn + j * 8;
            float2 b2 = *reinterpret_cast<const float2*>(bias + nn);
            float v00 = acc[i][j][0] + b2.x, v01 = acc[i][j][1] + b2.y;
            float v10 = acc[i][j][2] + b2.x, v11 = acc[i][j][3] + b2.y;
            if (nn < scale_limit) { v00 *= scale; v01 *= scale; v10 *= scale; v11 *= scale; }
            if (F32OUT) {
                float2 o0 = {v00, v01}, o1 = {v10, v11};
                *reinterpret_cast<float2*>(Cf + (size_t)(cm + i * 16    ) * N + nn) = o0;
                *reinterpret_cast<float2*>(Cf + (size_t)(cm + i * 16 + 8) * N + nn) = o1;
            } else {
                uint32_t h, l;
                size_t idx0 = ((size_t)(cm + i * 16) * N + nn) >> 1;
                size_t idx1 = ((size_t)(cm + i * 16 + 8) * N + nn) >> 1;
                cvt_hilo2(v00, v01, h, l);
                reinterpret_cast<uint32_t*>(Ch)[idx0] = h;
                reinterpret_cast<uint32_t*>(Cl)[idx0] = l;
                cvt_hilo2(v10, v11, h, l);
                reinterpret_cast<uint32_t*>(Ch)[idx1] = h;
                reinterpret_cast<uint32_t*>(Cl)[idx1] = l;
            }
        }
    }
}

// =====================================================================
// Fused dual attention: mma.sync, bf16x3, KV double-buffered (2 stages)
// =====================================================================
#define QB  128
#define KT  64
#define SRB 176
#define AQ_HI 0
#define AQ_LO (QB*SRB)
#define KV0   (2*QB*SRB)           // stage 0 base
#define TSZ   (KT*SRB)             // one tile buffer: 11264
#define KVST  (8*TSZ)              // stage size: 90112
// within-stage offsets
#define B_DKH 0
#define B_DKL (1*TSZ)
#define B_DVH (2*TSZ)
#define B_DVL (3*TSZ)
#define B_SKH (4*TSZ)
#define B_SKL (5*TSZ)
#define B_SVH (6*TSZ)
#define B_SVL (7*TSZ)
#define ATTN_SMEM (KV0 + 2*KVST)   // 225280 bytes

static __device__ __forceinline__ void cp_tile64(uint32_t dst, const char* src, int sstride, int tid) {
    for (int i = tid; i < 64 * 9; i += 256) {
        int r = i / 9, ch = i - r * 9;
        CP16(dst + (uint32_t)(r * SRB + ch * 16), src + (size_t)r * sstride + ch * 16);
    }
}

static __device__ __forceinline__ void load_tile_group(
    uint32_t stage_base, int b, int bh, int h, int k0, int tid)
{
    size_t dbase = ((size_t)(bh * NN + k0) * HD) * 2;
    cp_tile64(stage_base + B_DKH, (const char*)g_kd_hi + dbase, HD * 2, tid);
    cp_tile64(stage_base + B_DKL, (const char*)g_kd_lo + dbase, HD * 2, tid);
    cp_tile64(stage_base + B_DVH, (const char*)g_vd_hi + dbase, HD * 2, tid);
    cp_tile64(stage_base + B_DVL, (const char*)g_vd_lo + dbase, HD * 2, tid);
    size_t kb = ((size_t)(b * NN + k0) * C3 + CC + h * HD) * 2;
    size_t vb = ((size_t)(b * NN + k0) * C3 + 2 * CC + h * HD) * 2;
    cp_tile64(stage_base + B_SKH, (const char*)g_qkv_hi + kb, C3 * 2, tid);
    cp_tile64(stage_base + B_SKL, (const char*)g_qkv_lo + kb, C3 * 2, tid);
    cp_tile64(stage_base + B_SVH, (const char*)g_qkv_hi + vb, C3 * 2, tid);
    cp_tile64(stage_base + B_SVL, (const char*)g_qkv_lo + vb, C3 * 2, tid);
}

static __device__ __forceinline__ void compute_logits(
    float s[8][4], uint32_t sb, uint32_t khi_off, uint32_t klo_off, int lane, int wq0)
{
    #pragma unroll
    for (int tt = 0; tt < 8; tt++)
        #pragma unroll
        for (int q = 0; q < 4; q++) s[tt][q] = 0.f;

    const uint32_t qaddr = sb + (uint32_t)((wq0 + (lane & 15)) * SRB + (lane >> 4) * 16);
    const int ksub = lane >> 3, ki = lane & 7;
    const uint32_t kn_row = (uint32_t)(((ksub >> 1) << 3) + ki);
    const uint32_t kk_half = (uint32_t)((ksub & 1) * 16);

    #pragma unroll
    for (int ks = 0; ks < 5; ks++) {
        uint32_t ahr[4], alr[4];
        ldmatrix_x4(qaddr + AQ_HI + ks * 32, ahr[0], ahr[1], ahr[2], ahr[3]);
        ldmatrix_x4(qaddr + AQ_LO + ks * 32, alr[0], alr[1], alr[2], alr[3]);
        uint32_t bh_[8][2], bl_[8][2];
        #pragma unroll
        for (int g = 0; g < 4; g++) {
            uint32_t kaddr = (uint32_t)((g * 16 + kn_row) * SRB + ks * 32) + kk_half;
            uint32_t r0, r1, r2, r3;
            ldmatrix_x4(khi_off + kaddr, r0, r1, r2, r3);
            bh_[2*g][0] = r0; bh_[2*g][1] = r1; bh_[2*g+1][0] = r2; bh_[2*g+1][1] = r3;
            ldmatrix_x4(klo_off + kaddr, r0, r1, r2, r3);
            bl_[2*g][0] = r0; bl_[2*g][1] = r1; bl_[2*g+1][0] = r2; bl_[2*g+1][1] = r3;
        }
        #pragma unroll
        for (int tt = 0; tt < 8; tt++) mma_bf16(s[tt], ahr, bh_[tt]);
        #pragma unroll
        for (int tt = 0; tt < 8; tt++) mma_bf16(s[tt], ahr, bl_[tt]);
        #pragma unroll
        for (int tt = 0; tt < 8; tt++) mma_bf16(s[tt], alr, bh_[tt]);
    }
}

static __device__ __forceinline__ void softmax_pv(
    const float s[8][4], float p[8][4],
    float& m0, float& m1, float& l0, float& l1,
    float acc[9][4],
    uint32_t vhi_off, uint32_t vlo_off, int lane)
{
    float mx0 = -1e30f, mx1 = -1e30f;
    #pragma unroll
    for (int tt = 0; tt < 8; tt++) {
        mx0 = fmaxf(mx0, fmaxf(s[tt][0], s[tt][1]));
        mx1 = fmaxf(mx1, fmaxf(s[tt][2], s[tt][3]));
    }
    mx0 = fmaxf(mx0, __shfl_xor_sync(0xffffffffu, mx0, 1));
    mx0 = fmaxf(mx0, __shfl_xor_sync(0xffffffffu, mx0, 2));
    mx1 = fmaxf(mx1, __shfl_xor_sync(0xffffffffu, mx1, 1));
    mx1 = fmaxf(mx1, __shfl_xor_sync(0xffffffffu, mx1, 2));

    const float m0n = fmaxf(m0, mx0), m1n = fmaxf(m1, mx1);
    const float c0 = __expf(m0 - m0n), c1 = __expf(m1 - m1n);
    m0 = m0n; m1 = m1n;

    float r0 = 0.f, r1 = 0.f;
    #pragma unroll
    for (int tt = 0; tt < 8; tt++) {
        float p0 = __expf(s[tt][0] - m0n), p1 = __expf(s[tt][1] - m0n);
        float p2 = __expf(s[tt][2] - m1n), p3 = __expf(s[tt][3] - m1n);
        p[tt][0] = p0; p[tt][1] = p1; p[tt][2] = p2; p[tt][3] = p3;
        r0 += p0 + p1; r1 += p2 + p3;
    }
    r0 += __shfl_xor_sync(0xffffffffu, r0, 1);
    r0 += __shfl_xor_sync(0xffffffffu, r0, 2);
    r1 += __shfl_xor_sync(0xffffffffu, r1, 1);
    r1 += __shfl_xor_sync(0xffffffffu, r1, 2);
    l0 = l0 * c0 + r0;
    l1 = l1 * c1 + r1;

    #pragma unroll
    for (int tt = 0; tt < 9; tt++) {
        acc[tt][0] *= c0; acc[tt][1] *= c0;
        acc[tt][2] *= c1; acc[tt][3] *= c1;
    }

    const int vsub = lane >> 3, vi = lane & 7;
    #pragma unroll
    for (int j = 0; j < 4; j++) {
        uint32_t ahi[4], alo[4];
        cvt_hilo2(p[2*j][0],     p[2*j][1],     ahi[0], alo[0]);
        cvt_hilo2(p[2*j][2],     p[2*j][3],     ahi[1], alo[1]);
        cvt_hilo2(p[2*j + 1][0], p[2*j + 1][1], ahi[2], alo[2]);
        cvt_hilo2(p[2*j + 1][2], p[2*j + 1][3], ahi[3], alo[3]);
        const uint32_t krow = (uint32_t)(16 * j + vi + (vsub & 1) * 8);
        const uint32_t vrowa = krow * SRB + (uint32_t)((vsub >> 1) * 16);
        #pragma unroll
        for (int dpp = 0; dpp < 2; dpp++) {
            uint32_t va0 = vrowa + (uint32_t)(2 * dpp * 32);
            uint32_t va1 = va0 + 32;
            uint32_t vh0[4], vl0[4], vh1[4], vl1[4];
            ldmatrix_x4_trans(vhi_off + va0, vh0[0], vh0[1], vh0[2], vh0[3]);
            ldmatrix_x4_trans(vlo_off + va0, vl0[0], vl0[1], vl0[2], vl0[3]);
            ldmatrix_x4_trans(vhi_off + va1, vh1[0], vh1[1], vh1[2], vh1[3]);
            ldmatrix_x4_trans(vlo_off + va1, vl1[0], vl1[1], vl1[2], vl1[3]);
            float* a0 = acc[4*dpp+0]; float* a1 = acc[4*dpp+1];
            float* a2 = acc[4*dpp+2]; float* a3 = acc[4*dpp+3];
            mma_bf16(a0, ahi, vh0); mma_bf16(a1, ahi, vh0 + 2);
            mma_bf16(a2, ahi, vh1); mma_bf16(a3, ahi, vh1 + 2);
            mma_bf16(a0, ahi, vl0); mma_bf16(a1, ahi, vl0 + 2);
            mma_bf16(a2, ahi, vl1); mma_bf16(a3, ahi, vl1 + 2);
            mma_bf16(a0, alo, vh0); mma_bf16(a1, alo, vh0 + 2);
            mma_bf16(a2, alo, vh1); mma_bf16(a3, alo, vh1 + 2);
        }
        {
            uint32_t va = vrowa + 128;
            uint32_t vh[4], vl[4];
            ldmatrix_x4_trans(vhi_off + va, vh[0], vh[1], vh[2], vh[3]);
            ldmatrix_x4_trans(vlo_off + va, vl[0], vl[1], vl[2], vl[3]);
            mma_bf16(acc[8], ahi, vh);
            mma_bf16(acc[8], ahi, vl);
            mma_bf16(acc[8], alo, vh);
        }
    }
}

__global__ __launch_bounds__(256) void attn_mma_kernel()
{
    extern __shared__ char sm[];
    const uint32_t sb = smem_to_u32(sm);
    const int tid = threadIdx.x, lane = tid & 31, wid = tid >> 5;
    const int bh = blockIdx.y, b = bh >> 4, h = bh & 15;
    const int q0 = blockIdx.x * QB;
    const int wq0 = wid * 16;

    // zero pads (bytes 144..159 of each 176B row) across Q + both KV stages
    for (int r = tid; r < 2 * QB + 16 * KT; r += 256)
        *reinterpret_cast<uint4*>(sm + (size_t)r * SRB + 144) = make_uint4(0, 0, 0, 0);
    __syncthreads();

    // group 0: Q hi/lo + tile 0 KV (stage 0)
    {
        const char* qh = (const char*)g_qkv_hi + ((size_t)(b * NN + q0) * C3 + h * HD) * 2;
        const char* ql = (const char*)g_qkv_lo + ((size_t)(b * NN + q0) * C3 + h * HD) * 2;
        for (int i = tid; i < QB * 9; i += 256) {
            int r = i / 9, ch = i - r * 9;
            CP16(sb + AQ_HI + (uint32_t)(r * SRB + ch * 16), qh + (size_t)r * (C3 * 2) + ch * 16);
            CP16(sb + AQ_LO + (uint32_t)(r * SRB + ch * 16), ql + (size_t)r * (C3 * 2) + ch * 16);
        }
        load_tile_group(sb + KV0, b, bh, h, 0, tid);
        CP_COMMIT();
    }

    float accd[9][4], accs[9][4];
    #pragma unroll
    for (int tt = 0; tt < 9; tt++)
        #pragma unroll
        for (int q = 0; q < 4; q++) { accd[tt][q] = 0.f; accs[tt][q] = 0.f; }
    float md0 = -1e30f, md1 = -1e30f, ms0 = -1e30f, ms1 = -1e30f;
    float ld0 = 0.f, ld1 = 0.f, ls0 = 0.f, ls1 = 0.f;
    float Sdd0 = 0.f, Sdd1 = 0.f, Sss0 = 0.f, Sss1 = 0.f, Ssd0 = 0.f, Ssd1 = 0.f;

    float sd[8][4], ss[8][4];

    const int NT = NN / KT;
    for (int t = 0; t < NT; t++) {
        CP_WAIT0();            // tile t (and Q on t==0) arrived
        __syncthreads();

        if (t + 1 < NT)        // prefetch tile t+1 into other stage
        {
            load_tile_group(sb + KV0 + ((t + 1) & 1) * KVST, b, bh, h, (t + 1) * KT, tid);
            CP_COMMIT();
        }

        const uint32_t stg = sb + KV0 + (uint32_t)((t & 1) * KVST);

        // ---- grouped mma phase: both streams' logits ----
        compute_logits(sd, sb, stg + B_DKH, stg + B_DKL, lane, wq0);
        compute_logits(ss, sb, stg + B_SKH, stg + B_SKL, lane, wq0);

        // ---- cosine stats on raw logits ----
        #pragma unroll
        for (int tt = 0; tt < 8; tt++) {
            Sdd0 = fmaf(sd[tt][0], sd[tt][0], Sdd0); Sdd0 = fmaf(sd[tt][1], sd[tt][1], Sdd0);
            Sdd1 = fmaf(sd[tt][2], sd[tt][2], Sdd1); Sdd1 = fmaf(sd[tt][3], sd[tt][3], Sdd1);
            Sss0 = fmaf(ss[tt][0], ss[tt][0], Sss0); Sss0 = fmaf(ss[tt][1], ss[tt][1], Sss0);
            Sss1 = fmaf(ss[tt][2], ss[tt][2], Sss1); Sss1 = fmaf(ss[tt][3], ss[tt][3], Sss1);
            Ssd0 = fmaf(sd[tt][0], ss[tt][0], Ssd0); Ssd0 = fmaf(sd[tt][1], ss[tt][1], Ssd0);
            Ssd1 = fmaf(sd[tt][2], ss[tt][2], Ssd1); Ssd1 = fmaf(sd[tt][3], ss[tt][3], Ssd1);
        }

        // ---- softmax + PV, both streams (independent chains, interleavable) ----
        softmax_pv(sd, sd, md0, md1, ld0, ld1, accd, stg + B_DVH, stg + B_DVL, lane);
        softmax_pv(ss, ss, ms0, ms1, ls0, ls1, accs, stg + B_SVH, stg + B_SVL, lane);

        __syncthreads();       // all warps done reading stage t&1 before next overwrite cycle
    }

    // ---- finalize ----
    const float EPS = 1e-12f;
    const int r = lane >> 2, cq = (lane & 3) * 2;
    const int n0r = q0 + wq0 + r;
    const float inv0 = 1.0f / ls0, inv1 = 1.0f / ls1;
    uint32_t* oh = reinterpret_cast<uint32_t*>(g_at_hi);
    uint32_t* ol = reinterpret_cast<uint32_t*>(g_at_lo);
    #pragma unroll
    for (int tt = 0; tt < 9; tt++) {
        int col = tt * 8 + cq;
        size_t i0 = ((size_t)(b * NN + n0r) * CC + h * HD + col) >> 1;
        size_t i1 = ((size_t)(b * NN + n0r + 8) * CC + h * HD + col) >> 1;
        uint32_t hh, ll;
        cvt_hilo2(accs[tt][0] * inv0, accs[tt][1] * inv0, hh, ll);
        oh[i0] = hh; ol[i0] = ll;
        cvt_hilo2(accs[tt][2] * inv1, accs[tt][3] * inv1, hh, ll);
        oh[i1] = hh; ol[i1] = ll;
    }

    float dd0 = 0.f, ss0 = 0.f, xs0 = 0.f, dd1 = 0.f, ss1 = 0.f, xs1 = 0.f;
    #pragma unroll
    for (int tt = 0; tt < 9; tt++) {
        dd0 = fmaf(accd[tt][0], accd[tt][0], dd0); dd0 = fmaf(accd[tt][1], accd[tt][1], dd0);
        ss0 = fmaf(accs[tt][0], accs[tt][0], ss0); ss0 = fmaf(accs[tt][1], accs[tt][1], ss0);
        xs0 = fmaf(accd[tt][0], accs[tt][0], xs0); xs0 = fmaf(accd[tt][1], accs[tt][1], xs0);
        dd1 = fmaf(accd[tt][2], accd[tt][2], dd1); dd1 = fmaf(accd[tt][3], accd[tt][3], dd1);
        ss1 = fmaf(accs[tt][2], accs[tt][2], ss1); ss1 = fmaf(accs[tt][3], accs[tt][3], ss1);
        xs1 = fmaf(accd[tt][2], accs[tt][2], xs1); xs1 = fmaf(accd[tt][3], accs[tt][3], xs1);
    }
    #pragma unroll
    for (int o = 1; o <= 2; o <<= 1) {
        Sdd0 += __shfl_xor_sync(0xffffffffu, Sdd0, o);
        Sss0 += __shfl_xor_sync(0xffffffffu, Sss0, o);
        Ssd0 += __shfl_xor_sync(0xffffffffu, Ssd0, o);
        Sdd1 += __shfl_xor_sync(0xffffffffu, Sdd1, o);
        Sss1 += __shfl_xor_sync(0xffffffffu, Sss1, o);
        Ssd1 += __shfl_xor_sync(0xffffffffu, Ssd1, o);
        dd0 += __shfl_xor_sync(0xffffffffu, dd0, o);
        ss0 += __shfl_xor_sync(0xffffffffu, ss0, o);
        xs0 += __shfl_xor_sync(0xffffffffu, xs0, o);
        dd1 += __shfl_xor_sync(0xffffffffu, dd1, o);
        ss1 += __shfl_xor_sync(0xffffffffu, ss1, o);
        xs1 += __shfl_xor_sync(0xffffffffu, xs1, o);
    }
    if ((lane & 3) == 0) {
        float cosL0 = Ssd0 / (fmaxf(sqrtf(Sdd0), EPS) * fmaxf(sqrtf(Sss0), EPS));
        float cosL1 = Ssd1 / (fmaxf(sqrtf(Sdd1), EPS) * fmaxf(sqrtf(Sss1), EPS));
        float cosA0 = xs0 / (fmaxf(sqrtf(dd0), EPS) * fmaxf(sqrtf(ss0), EPS));
        float cosA1 = xs1 / (fmaxf(sqrtf(dd1), EPS) * fmaxf(sqrtf(ss1), EPS));
        g_cosL[bh * NN + n0r]     = cosL0;
        g_cosL[bh * NN + n0r + 8] = cosL1;
        g_cosA[bh * NN + n0r]     = cosA0;
        g_cosA[bh * NN + n0r + 8] = cosA1;
    }
}

// ---------------- deterministic loss reduction ----------------
__global__ __launch_bounds__(1024) void loss_kernel(float* __restrict__ out, int out_size)
{
    __shared__ float sL[1024], sA[1024];
    int t = threadIdx.x;
    float aL = 0.f, aA = 0.f;
    for (int i = t; i < NROWS; i += 1024) { aL += g_cosL[i]; aA += g_cosA[i]; }
    sL[t] = aL; sA[t] = aA;
    __syncthreads();
    for (int s = 512; s > 0; s >>= 1) {
        if (t < s) { sL[t] += sL[t + s]; sA[t] += sA[t + s]; }
        __syncthreads();
    }
    if (t == 0) {
        float meanL = sL[0] / (float)NROWS;
        float meanA = sA[0] / (float)NROWS;
        out[out_size - 1] = 1.5f - meanL - 0.5f * meanA;
    }
}

// ---------------- launch ----------------
extern "C" void kernel_launch(void* const* d_in, const int* in_sizes, int n_in,
                              void* d_out, int out_size)
{
    const float* x      = (const float*)d_in[0];
    const float* qkv_w  = (const float*)d_in[1];
    const float* qkv_b  = (const float*)d_in[2];
    const float* proj_w = (const float*)d_in[3];
    const float* proj_b = (const float*)d_in[4];
    const float* k_dino = (const float*)d_in[5];
    const float* v_dino = (const float*)d_in[6];
    float* out = (float*)d_out;

    const float scale = 0.11785113019775793f;   // 1/sqrt(72)

    __nv_bfloat16 *xh, *xl, *w1h, *w1l, *w2h, *w2l;
    __nv_bfloat16 *qh, *ql, *ath, *atl;
    cudaGetSymbolAddress((void**)&xh,  g_x_hi);  cudaGetSymbolAddress((void**)&xl,  g_x_lo);
    cudaGetSymbolAddress((void**)&w1h, g_w1_hi); cudaGetSymbolAddress((void**)&w1l, g_w1_lo);
    cudaGetSymbolAddress((void**)&w2h, g_w2_hi); cudaGetSymbolAddress((void**)&w2l, g_w2_lo);
    cudaGetSymbolAddress((void**)&qh,  g_qkv_hi); cudaGetSymbolAddress((void**)&ql,  g_qkv_lo);
    cudaGetSymbolAddress((void**)&ath, g_at_hi);  cudaGetSymbolAddress((void**)&atl, g_at_lo);

    cudaFuncSetAttribute(gemm_mma<false>, cudaFuncAttributeMaxDynamicSharedMemorySize, GEMM_SMEM);
    cudaFuncSetAttribute(gemm_mma<true>,  cudaFuncAttributeMaxDynamicSharedMemorySize, GEMM_SMEM);
    cudaFuncSetAttribute(attn_mma_kernel, cudaFuncAttributeMaxDynamicSharedMemorySize, ATTN_SMEM);

    // 0) fused prep conversions (one launch)
    cvt_all_kernel<<<(NTOT + 255) / 256, 256>>>(x, qkv_w, proj_w, k_dino, v_dino);

    // 1) qkv = x @ qkv_w^T + qkv_b  (bf16 hi/lo out; Q cols prescaled)
    {
        dim3 grid(C3 / TBN, (BB * NN) / TBM);
        gemm_mma<false><<<grid, 256, GEMM_SMEM>>>(xh, xl, w1h, w1l, qkv_b,
                                                  nullptr, qh, ql,
                                                  BB * NN, C3, CC, CC, scale);
    }
    // 2) fused dual attention + alignment stats
    {
        dim3 grid(NN / QB, BB * HH);
        attn_mma_kernel<<<grid, 256, ATTN_SMEM>>>();
    }
    // 3) out = attn @ proj_w^T + proj_b  (f32 out)
    {
        dim3 grid(CC / TBN, (BB * NN) / TBM);
        gemm_mma<true><<<grid, 256, GEMM_SMEM>>>(ath, atl, w2h, w2l, proj_b,
                                                 out, nullptr, nullptr,
                                                 BB * NN, CC, CC, 0, 1.0f);
    }
    // 4) distill loss
    loss_kernel<<<1, 1024>>>(out, out_size);
}